// round 12
// baseline (speedup 1.0000x reference)
#include <cuda_runtime.h>
#include <cuda_fp16.h>
#include <math.h>
#include <stdint.h>

#define NB 4
#define CC 256
#define HWD 4096
#define NH 4
#define HD 64
#define NGRP 8
#define GC 32
#define EPSV 1e-5f
#define LOG2E 1.44269504088896340736f
#define NSPLIT 4
#define SPLIT_OFF (NB * CC * HWD)
#define CHUNKS_PER_SPLIT (64 / NSPLIT)

// ---- scratch (allocation-free) ----
__device__ __half g_q16[NB * CC * HWD];
__device__ __half g_k16[NB * CC * HWD];
__device__ __half g_v16[NB * CC * HWD];
__device__ __half g_ao16[NB * CC * HWD];
__device__ __half g_qw16[3 * CC * CC];
__device__ __half g_pw16[CC * CC];
__device__ float  g_part[256 * 2];
__device__ __half g_po16[NSPLIT * NB * CC * HWD];   // partial O (f16, un-normalized)
__device__ float  g_pl[NSPLIT * NB * NH * HWD];     // partial l (f32)

// ---------------- helpers ----------------
__device__ __forceinline__ uint32_t h2ex2(uint32_t x) {
    uint32_t y; asm("ex2.approx.f16x2 %0, %1;" : "=r"(y) : "r"(x)); return y;
}
__device__ __forceinline__ uint32_t pack2(float a, float b) {
    __half2 h = __floats2half2_rn(a, b);
    return *reinterpret_cast<uint32_t*>(&h);
}
__device__ __forceinline__ __half2 u2h(uint32_t u) { return *reinterpret_cast<__half2*>(&u); }
__device__ __forceinline__ uint32_t sptr(const void* p) {
    return (uint32_t)__cvta_generic_to_shared(p);
}
__device__ __forceinline__ void cp16(void* dst, const void* src) {
    asm volatile("cp.async.cg.shared.global [%0], [%1], 16;\n"
                 :: "r"(sptr(dst)), "l"(src));
}
__device__ __forceinline__ void ldsm4t(uint32_t* f, const void* p) {
    asm volatile("ldmatrix.sync.aligned.m8n8.x4.trans.shared.b16 {%0,%1,%2,%3}, [%4];\n"
                 : "=r"(f[0]), "=r"(f[1]), "=r"(f[2]), "=r"(f[3]) : "r"(sptr(p)));
}
__device__ __forceinline__ void ldsm4(uint32_t* f, const void* p) {
    asm volatile("ldmatrix.sync.aligned.m8n8.x4.shared.b16 {%0,%1,%2,%3}, [%4];\n"
                 : "=r"(f[0]), "=r"(f[1]), "=r"(f[2]), "=r"(f[3]) : "r"(sptr(p)));
}
__device__ __forceinline__ void mma16816(float* c, const uint32_t* a, uint32_t b0, uint32_t b1) {
    asm volatile(
        "mma.sync.aligned.m16n8k16.row.col.f32.f16.f16.f32 "
        "{%0,%1,%2,%3}, {%4,%5,%6,%7}, {%8,%9}, {%0,%1,%2,%3};\n"
        : "+f"(c[0]), "+f"(c[1]), "+f"(c[2]), "+f"(c[3])
        : "r"(a[0]), "r"(a[1]), "r"(a[2]), "r"(a[3]), "r"(b0), "r"(b1));
}
__device__ __forceinline__ void mma16816h(uint32_t* c, const uint32_t* a, uint32_t b0, uint32_t b1) {
    asm volatile(
        "mma.sync.aligned.m16n8k16.row.col.f16.f16.f16.f16 "
        "{%0,%1}, {%2,%3,%4,%5}, {%6,%7}, {%0,%1};\n"
        : "+r"(c[0]), "+r"(c[1])
        : "r"(a[0]), "r"(a[1]), "r"(a[2]), "r"(a[3]), "r"(b0), "r"(b1));
}

// ---------------- GroupNorm partials + weight conversion (fused launch) ----------------
__global__ void gn_conv_kernel(const float* __restrict__ x,
                               const float* __restrict__ qw, const float* __restrict__ pw) {
    if (blockIdx.x >= 256) {
        int i = (blockIdx.x - 256) * 256 + threadIdx.x;
        if (i < 3 * CC * CC) g_qw16[i] = __float2half(qw[i]);
        if (i < CC * CC)     g_pw16[i] = __float2half(pw[i]);
        return;
    }
    int ng = blockIdx.x >> 3, part = blockIdx.x & 7;
    const float4* xp = (const float4*)(x + (size_t)ng * GC * HWD);
    float s = 0.f, ss = 0.f;
    int i0 = part * 4096;
    for (int i = i0 + threadIdx.x; i < i0 + 4096; i += 256) {
        float4 v = xp[i];
        s  += v.x + v.y + v.z + v.w;
        ss += v.x * v.x + v.y * v.y + v.z * v.z + v.w * v.w;
    }
    #pragma unroll
    for (int off = 16; off; off >>= 1) {
        s  += __shfl_down_sync(0xffffffffu, s, off);
        ss += __shfl_down_sync(0xffffffffu, ss, off);
    }
    __shared__ float sh[16];
    int w = threadIdx.x >> 5;
    if ((threadIdx.x & 31) == 0) { sh[w] = s; sh[8 + w] = ss; }
    __syncthreads();
    if (threadIdx.x == 0) {
        float S = 0.f, SS = 0.f;
        #pragma unroll
        for (int i = 0; i < 8; i++) { S += sh[i]; SS += sh[8 + i]; }
        g_part[blockIdx.x * 2] = S; g_part[blockIdx.x * 2 + 1] = SS;
    }
}

// ---------------- fused GN + QKV GEMM (fp16 tensor core) ----------------
#define GA_ST 5120
#define GB_OFF (3 * GA_ST)
#define GB_ST 4352
#define QKV_SMEM ((GB_OFF + 2 * GB_ST) * 2)

__global__ __launch_bounds__(256, 2) void gemm_qkv16_kernel(
    const float* __restrict__ x,
    const float* __restrict__ nw, const float* __restrict__ nb_,
    const float* __restrict__ qkv_b)
{
    extern __shared__ __align__(16) __half GS[];
    __shared__ float sc[CC], bc[CC];
    const int n  = blockIdx.z;
    const int o0 = blockIdx.y * 128;
    const int j0 = blockIdx.x * 128;

    const int tid = threadIdx.x, w = tid >> 5, lane = tid & 31;
    const int wm = w >> 1, wn = w & 1;
    const int g = lane >> 2, t4 = lane & 3, mi = lane >> 3, r8 = lane & 7;
    const int la = lane & 15, ha = lane >> 4;

    {
        int c = tid;
        int ng = n * NGRP + c / GC;
        float s = 0.f, ss = 0.f;
        #pragma unroll
        for (int p = 0; p < 8; p++) {
            s  += g_part[(ng * 8 + p) * 2];
            ss += g_part[(ng * 8 + p) * 2 + 1];
        }
        const float invn = 1.0f / (float)(GC * HWD);
        float m  = s * invn;
        float rs = rsqrtf(ss * invn - m * m + EPSV);
        float scv = rs * nw[c];
        sc[c] = scv;
        bc[c] = nb_[c] - m * scv;
    }

    auto prefetchA = [&](int buf, int k0) {
        __half* Ab = GS + buf * GA_ST;
        #pragma unroll
        for (int i = 0; i < 2; i++) {
            int s = tid + 256 * i;
            int row = s >> 2, c8 = (s & 3) * 8;
            cp16(&Ab[row * 40 + c8], &g_qw16[(size_t)(o0 + row) * CC + k0 + c8]);
        }
        asm volatile("cp.async.commit_group;\n");
    };

    const float* xb = x + (size_t)n * CC * HWD;
    const int brow = tid >> 3;
    const int bj   = (tid & 7) * 16;
    uint32_t breg[8];
    auto loadB = [&](int k0) {
        float scv = sc[k0 + brow], bcv = bc[k0 + brow];
        const float* src = xb + (size_t)(k0 + brow) * HWD + j0 + bj;
        #pragma unroll
        for (int i = 0; i < 4; i++) {
            float4 v = *(const float4*)(src + 4 * i);
            breg[2 * i]     = pack2(v.x * scv + bcv, v.y * scv + bcv);
            breg[2 * i + 1] = pack2(v.z * scv + bcv, v.w * scv + bcv);
        }
    };
    auto stsB = [&](int buf) {
        __half* Bb = GS + GB_OFF + buf * GB_ST;
        *(uint4*)&Bb[brow * 136 + bj]     = *(uint4*)&breg[0];
        *(uint4*)&Bb[brow * 136 + bj + 8] = *(uint4*)&breg[4];
    };

    prefetchA(0, 0);
    prefetchA(1, 32);
    __syncthreads();
    loadB(0);

    float acc[2][8][4] = {};
    for (int c = 0; c < 8; c++) {
        stsB(c & 1);
        if (c < 7)  asm volatile("cp.async.wait_group 1;\n");
        else        asm volatile("cp.async.wait_group 0;\n");
        __syncthreads();
        if (c + 2 < 8) prefetchA((c + 2) % 3, (c + 2) * 32);
        if (c + 1 < 8) loadB((c + 1) * 32);

        __half* Ab = GS + (c % 3) * GA_ST;
        __half* Bb = GS + GB_OFF + (c & 1) * GB_ST;
        #pragma unroll
        for (int ks = 0; ks < 2; ks++) {
            uint32_t a[2][4];
            #pragma unroll
            for (int mt = 0; mt < 2; mt++)
                ldsm4(a[mt], &Ab[(wm * 32 + mt * 16 + la) * 40 + ks * 16 + ha * 8]);
            #pragma unroll
            for (int nb = 0; nb < 4; nb++) {
                uint32_t b[4];
                ldsm4t(b, &Bb[(ks * 16 + (mi & 1) * 8 + r8) * 136 + wn * 64 + nb * 16 + (mi >> 1) * 8]);
                #pragma unroll
                for (int mt = 0; mt < 2; mt++) {
                    mma16816(acc[mt][2 * nb],     a[mt], b[0], b[1]);
                    mma16816(acc[mt][2 * nb + 1], a[mt], b[2], b[3]);
                }
            }
        }
        __syncthreads();
    }

    const int part = o0 >> 8;
    __half* dst = (part == 0) ? g_q16 : ((part == 1) ? g_k16 : g_v16);
    const float scale = (part == 0) ? (0.125f * LOG2E) : 1.0f;
    #pragma unroll
    for (int mt = 0; mt < 2; mt++) {
        int o_lo = o0 + wm * 32 + mt * 16 + g;
        float b_lo = qkv_b[o_lo], b_hi = qkv_b[o_lo + 8];
        int c_lo = o_lo & 255;
        #pragma unroll
        for (int nt = 0; nt < 8; nt++) {
            int j = j0 + wn * 64 + nt * 8 + 2 * t4;
            *(uint32_t*)&dst[((size_t)n * CC + c_lo) * HWD + j] =
                pack2((acc[mt][nt][0] + b_lo) * scale, (acc[mt][nt][1] + b_lo) * scale);
            *(uint32_t*)&dst[((size_t)n * CC + c_lo + 8) * HWD + j] =
                pack2((acc[mt][nt][2] + b_hi) * scale, (acc[mt][nt][3] + b_hi) * scale);
        }
    }
}

// ---------------- proj GEMM + residual + mask (+ mask-copy blocks) ----------------
#define PROJ_SMEM ((GB_OFF + 3 * GB_ST) * 2)

__global__ __launch_bounds__(256, 2) void gemm_proj16_kernel(
    const float* __restrict__ x, const float* __restrict__ mask,
    const float* __restrict__ pb, float* __restrict__ out)
{
    extern __shared__ __align__(16) __half GS[];
    const int n  = blockIdx.z;
    const int j0 = blockIdx.x * 128;

    if (blockIdx.y == 2) {
        if (threadIdx.x < 128) {
            float* mout = out + (size_t)NB * CC * HWD;
            int idx = n * HWD + j0 + threadIdx.x;
            mout[idx] = mask[idx];
        }
        return;
    }
    const int o0 = blockIdx.y * 128;

    const int tid = threadIdx.x, w = tid >> 5, lane = tid & 31;
    const int wm = w >> 1, wn = w & 1;
    const int g = lane >> 2, t4 = lane & 3, mi = lane >> 3, r8 = lane & 7;
    const int la = lane & 15, ha = lane >> 4;
    const __half* Bsrc = g_ao16 + (size_t)n * CC * HWD;

    auto prefetch = [&](int buf, int k0) {
        __half* Ab = GS + buf * GA_ST;
        __half* Bb = GS + GB_OFF + buf * GB_ST;
        #pragma unroll
        for (int i = 0; i < 2; i++) {
            int s = tid + 256 * i;
            int row = s >> 2, c8 = (s & 3) * 8;
            cp16(&Ab[row * 40 + c8], &g_pw16[(size_t)(o0 + row) * CC + k0 + c8]);
        }
        #pragma unroll
        for (int i = 0; i < 2; i++) {
            int s = tid + 256 * i;
            int row = s >> 4, c8 = (s & 15) * 8;
            cp16(&Bb[row * 136 + c8], &Bsrc[(size_t)(k0 + row) * HWD + j0 + c8]);
        }
        asm volatile("cp.async.commit_group;\n");
    };

    float acc[2][8][4] = {};
    prefetch(0, 0);
    prefetch(1, 32);
    for (int c = 0; c < 8; c++) {
        if (c < 7) asm volatile("cp.async.wait_group 1;\n");
        else       asm volatile("cp.async.wait_group 0;\n");
        __syncthreads();
        if (c + 2 < 8) prefetch((c + 2) % 3, (c + 2) * 32);
        int buf = c % 3;
        __half* Ab = GS + buf * GA_ST;
        __half* Bb = GS + GB_OFF + buf * GB_ST;
        #pragma unroll
        for (int ks = 0; ks < 2; ks++) {
            uint32_t a[2][4];
            #pragma unroll
            for (int mt = 0; mt < 2; mt++)
                ldsm4(a[mt], &Ab[(wm * 32 + mt * 16 + la) * 40 + ks * 16 + ha * 8]);
            #pragma unroll
            for (int nb = 0; nb < 4; nb++) {
                uint32_t b[4];
                ldsm4t(b, &Bb[(ks * 16 + (mi & 1) * 8 + r8) * 136 + wn * 64 + nb * 16 + (mi >> 1) * 8]);
                #pragma unroll
                for (int mt = 0; mt < 2; mt++) {
                    mma16816(acc[mt][2 * nb],     a[mt], b[0], b[1]);
                    mma16816(acc[mt][2 * nb + 1], a[mt], b[2], b[3]);
                }
            }
        }
    }

    #pragma unroll
    for (int mt = 0; mt < 2; mt++) {
        int o_lo = o0 + wm * 32 + mt * 16 + g;
        float b_lo = pb[o_lo], b_hi = pb[o_lo + 8];
        #pragma unroll
        for (int nt = 0; nt < 8; nt++) {
            int j = j0 + wn * 64 + nt * 8 + 2 * t4;
            float2 mv = *(const float2*)&mask[(size_t)n * HWD + j];
            size_t off = ((size_t)n * CC + o_lo) * HWD + j;
            float2 xv = *(const float2*)&x[off];
            float2 r;
            r.x = (xv.x + acc[mt][nt][0] + b_lo) * mv.x;
            r.y = (xv.y + acc[mt][nt][1] + b_lo) * mv.y;
            *(float2*)&out[off] = r;
            size_t off2 = off + 8 * HWD;
            float2 xv2 = *(const float2*)&x[off2];
            float2 r2;
            r2.x = (xv2.x + acc[mt][nt][2] + b_hi) * mv.x;
            r2.y = (xv2.y + acc[mt][nt][3] + b_hi) * mv.y;
            *(float2*)&out[off2] = r2;
        }
    }
}

// ---------------- Flash attention: split-K x4, fixed-bias softmax, f16 partials ----------------
#define KP 72
#define QP 136
#define BIAS_H2 0xC800C800u   // f16x2 {-8, -8}
__global__ __launch_bounds__(128, 3) void attn_kernel() {
    __shared__ __align__(16) __half SMh[18432];   // 36864 B
    const int n = blockIdx.y >> 2, h = blockIdx.y & 3;
    const int q0 = blockIdx.x * 128;
    const int split = blockIdx.z;
    const int c0 = split * CHUNKS_PER_SPLIT;
    const size_t base = (size_t)(n * CC + h * HD) * HWD;
    const __half* qg = g_q16 + base;
    const __half* kg = g_k16 + base;
    const __half* vg = g_v16 + base;

    const int tid = threadIdx.x, w = tid >> 5, lane = tid & 31;
    const int g = lane >> 2, t4 = lane & 3, mi = lane >> 3, r8 = lane & 7;

    #pragma unroll
    for (int i = 0; i < 8; i++) {
        int s = tid + 128 * i;
        int row = s >> 4, c8 = (s & 15) * 8;
        *(uint4*)&SMh[row * QP + c8] = *(const uint4*)&qg[(size_t)row * HWD + q0 + c8];
    }
    __syncthreads();
    uint32_t aq[2][4][4];
    #pragma unroll
    for (int mt = 0; mt < 2; mt++)
        #pragma unroll
        for (int kt = 0; kt < 4; kt++)
            ldsm4t(aq[mt][kt],
                   &SMh[(kt * 16 + (mi >> 1) * 8 + r8) * QP + w * 32 + mt * 16 + (mi & 1) * 8]);
    __syncthreads();

    auto prefetch = [&](int buf, int c) {
        int jc = c * 64;
        __half* Kb = &SMh[buf * 4608];
        __half* Vb = &SMh[9216 + buf * 4608];
        #pragma unroll
        for (int i = 0; i < 4; i++) {
            int s = tid + 128 * i;
            int row = s >> 3, c8 = (s & 7) * 8;
            cp16(&Kb[row * KP + c8], &kg[(size_t)row * HWD + jc + c8]);
            cp16(&Vb[row * KP + c8], &vg[(size_t)row * HWD + jc + c8]);
        }
        asm volatile("cp.async.commit_group;\n");
    };

    float o_[2][8][4] = {};
    float l[2][2] = {};

    prefetch(0, c0);
    for (int c = c0; c < c0 + CHUNKS_PER_SPLIT; c++) {
        int buf = c & 1;
        if (c + 1 < c0 + CHUNKS_PER_SPLIT) { prefetch(buf ^ 1, c + 1); asm volatile("cp.async.wait_group 1;\n"); }
        else                               { asm volatile("cp.async.wait_group 0;\n"); }
        __syncthreads();
        const __half* Kb = &SMh[buf * 4608];
        const __half* Vb = &SMh[9216 + buf * 4608];

        // S = Q K^T + (-8), f16 accumulators
        uint32_t s[2][8][2];
        #pragma unroll
        for (int mt = 0; mt < 2; mt++)
            #pragma unroll
            for (int nt = 0; nt < 8; nt++) { s[mt][nt][0] = BIAS_H2; s[mt][nt][1] = BIAS_H2; }
        #pragma unroll
        for (int kt = 0; kt < 4; kt++) {
            #pragma unroll
            for (int ntp = 0; ntp < 4; ntp++) {
                uint32_t b[4];
                ldsm4t(b, &Kb[(kt * 16 + (mi & 1) * 8 + r8) * KP + ntp * 16 + (mi >> 1) * 8]);
                #pragma unroll
                for (int mt = 0; mt < 2; mt++) {
                    mma16816h(s[mt][2 * ntp],     aq[mt][kt], b[0], b[1]);
                    mma16816h(s[mt][2 * ntp + 1], aq[mt][kt], b[2], b[3]);
                }
            }
        }

        // p = exp2(s - 8) in place; accumulate row sums
        #pragma unroll
        for (int mt = 0; mt < 2; mt++) {
            __half2 hs0 = __floats2half2_rn(0.f, 0.f), hs1 = hs0;
            #pragma unroll
            for (int nt = 0; nt < 8; nt++) {
                uint32_t p0 = h2ex2(s[mt][nt][0]);
                uint32_t p1 = h2ex2(s[mt][nt][1]);
                s[mt][nt][0] = p0; s[mt][nt][1] = p1;
                hs0 = __hadd2(hs0, u2h(p0));
                hs1 = __hadd2(hs1, u2h(p1));
            }
            l[mt][0] += __low2float(hs0) + __high2float(hs0);
            l[mt][1] += __low2float(hs1) + __high2float(hs1);
        }

        // O += P V   (P aliases S)
        #pragma unroll
        for (int kt = 0; kt < 4; kt++) {
            #pragma unroll
            for (int ntp = 0; ntp < 4; ntp++) {
                uint32_t b[4];
                ldsm4(b, &Vb[(ntp * 16 + (mi >> 1) * 8 + r8) * KP + kt * 16 + (mi & 1) * 8]);
                #pragma unroll
                for (int mt = 0; mt < 2; mt++) {
                    uint32_t ap[4] = { s[mt][2 * kt][0], s[mt][2 * kt][1],
                                       s[mt][2 * kt + 1][0], s[mt][2 * kt + 1][1] };
                    mma16816(o_[mt][2 * ntp],     ap, b[0], b[1]);
                    mma16816(o_[mt][2 * ntp + 1], ap, b[2], b[3]);
                }
            }
        }
        __syncthreads();
    }

    // partial epilogue: quad row sums for l, write l (f32) + un-normalized O (f16)
    #pragma unroll
    for (int mt = 0; mt < 2; mt++)
        #pragma unroll
        for (int hh = 0; hh < 2; hh++) {
            l[mt][hh] += __shfl_xor_sync(0xffffffffu, l[mt][hh], 1);
            l[mt][hh] += __shfl_xor_sync(0xffffffffu, l[mt][hh], 2);
        }
    float* pl = g_pl + (size_t)split * NB * NH * HWD + (size_t)(n * NH + h) * HWD + q0;
    if (t4 == 0) {
        #pragma unroll
        for (int mt = 0; mt < 2; mt++) {
            int qr = w * 32 + mt * 16 + g;
            pl[qr]     = l[mt][0];
            pl[qr + 8] = l[mt][1];
        }
    }

    __syncthreads();
    // stage un-normalized O as f16 [q][d] (stride KP), then transposed coalesced store
    #pragma unroll
    for (int mt = 0; mt < 2; mt++) {
        int qr = w * 32 + mt * 16 + g;
        #pragma unroll
        for (int nt = 0; nt < 8; nt++) {
            int d0 = nt * 8 + 2 * t4;
            *(uint32_t*)&SMh[qr * KP + d0]       = pack2(o_[mt][nt][0], o_[mt][nt][1]);
            *(uint32_t*)&SMh[(qr + 8) * KP + d0] = pack2(o_[mt][nt][2], o_[mt][nt][3]);
        }
    }
    __syncthreads();
    __half* po = g_po16 + (size_t)split * SPLIT_OFF + base;
    #pragma unroll
    for (int i = 0; i < 32; i++) {
        int f = tid + 128 * i;
        int qp = f & 63, d = f >> 6;
        __half2 hv = __halves2half2(SMh[(2 * qp) * KP + d], SMh[(2 * qp + 1) * KP + d]);
        *(uint32_t*)&po[(size_t)d * HWD + q0 + 2 * qp] = *(uint32_t*)&hv;
    }
}

// ---------------- split-K reduce: ao16 = (ΣO_i)/(Σl_i) ----------------
__global__ void attn_reduce_kernel() {
    size_t idx = ((size_t)blockIdx.x * 256 + threadIdx.x) * 4;   // 4 halves per thread
    int row = (int)(idx >> 12);        // n*CC + c
    int n = row >> 8, c = row & 255;
    int nh = n * NH + (c >> 6);
    int q = (int)(idx & 4095);

    float o0 = 0.f, o1 = 0.f, o2 = 0.f, o3 = 0.f;
    float l0 = 0.f, l1 = 0.f, l2 = 0.f, l3 = 0.f;
    #pragma unroll
    for (int sp = 0; sp < NSPLIT; sp++) {
        uint2 u = *(const uint2*)&g_po16[(size_t)sp * SPLIT_OFF + idx];
        __half2 a = u2h(u.x), b = u2h(u.y);
        o0 += __low2float(a); o1 += __high2float(a);
        o2 += __low2float(b); o3 += __high2float(b);
        const float* pl = g_pl + (size_t)sp * NB * NH * HWD + (size_t)nh * HWD + q;
        float4 lv = *(const float4*)pl;
        l0 += lv.x; l1 += lv.y; l2 += lv.z; l3 += lv.w;
    }
    uint2 o;
    o.x = pack2(o0 / l0, o1 / l1);
    o.y = pack2(o2 / l2, o3 / l3);
    *(uint2*)&g_ao16[idx] = o;
}

// ---------------------------------------------------------------------------
extern "C" void kernel_launch(void* const* d_in, const int* in_sizes, int n_in,
                              void* d_out, int out_size) {
    const float* x      = (const float*)d_in[0];
    const float* mask   = (const float*)d_in[1];
    const float* norm_w = (const float*)d_in[2];
    const float* norm_b = (const float*)d_in[3];
    const float* qkv_w  = (const float*)d_in[4];
    const float* qkv_b  = (const float*)d_in[5];
    const float* proj_w = (const float*)d_in[6];
    const float* proj_b = (const float*)d_in[7];
    float* out = (float*)d_out;

    cudaFuncSetAttribute(gemm_qkv16_kernel,  cudaFuncAttributeMaxDynamicSharedMemorySize, QKV_SMEM);
    cudaFuncSetAttribute(gemm_proj16_kernel, cudaFuncAttributeMaxDynamicSharedMemorySize, PROJ_SMEM);

    gn_conv_kernel<<<256 + 1024, 256>>>(x, qkv_w, proj_w);
    gemm_qkv16_kernel<<<dim3(HWD / 128, (3 * CC) / 128, NB), 256, QKV_SMEM>>>(x, norm_w, norm_b, qkv_b);
    attn_kernel<<<dim3(HWD / 128, NB * NH, NSPLIT), 128>>>();
    attn_reduce_kernel<<<(NB * CC * HWD) / (256 * 4), 256>>>();
    int ny = (out_size >= NB * CC * HWD + NB * HWD) ? 3 : 2;
    gemm_proj16_kernel<<<dim3(HWD / 128, ny, NB), 256, PROJ_SMEM>>>(x, mask, proj_b, out);
}

// round 13
// speedup vs baseline: 1.0298x; 1.0298x over previous
#include <cuda_runtime.h>
#include <cuda_fp16.h>
#include <math.h>
#include <stdint.h>

#define NB 4
#define CC 256
#define HWD 4096
#define NH 4
#define HD 64
#define NGRP 8
#define GC 32
#define EPSV 1e-5f
#define LOG2E 1.44269504088896340736f
#define NSPLIT 2
#define SPLIT_OFF (NB * CC * HWD)
#define CHUNKS_PER_SPLIT (64 / NSPLIT)

// ---- scratch (allocation-free) ----
__device__ __half g_q16[NB * CC * HWD];
__device__ __half g_k16[NB * CC * HWD];
__device__ __half g_v16[NB * CC * HWD];
__device__ __half g_qw16[3 * CC * CC];
__device__ __half g_pw16[CC * CC];
__device__ float  g_part[256 * 2];
__device__ __half g_po16[NSPLIT * NB * CC * HWD];   // partial O (f16, un-normalized)
__device__ float  g_pl[NSPLIT * NB * NH * HWD];     // partial l (f32)

// ---------------- helpers ----------------
__device__ __forceinline__ uint32_t h2ex2(uint32_t x) {
    uint32_t y; asm("ex2.approx.f16x2 %0, %1;" : "=r"(y) : "r"(x)); return y;
}
__device__ __forceinline__ uint32_t pack2(float a, float b) {
    __half2 h = __floats2half2_rn(a, b);
    return *reinterpret_cast<uint32_t*>(&h);
}
__device__ __forceinline__ __half2 u2h(uint32_t u) { return *reinterpret_cast<__half2*>(&u); }
__device__ __forceinline__ uint32_t sptr(const void* p) {
    return (uint32_t)__cvta_generic_to_shared(p);
}
__device__ __forceinline__ void cp16(void* dst, const void* src) {
    asm volatile("cp.async.cg.shared.global [%0], [%1], 16;\n"
                 :: "r"(sptr(dst)), "l"(src));
}
__device__ __forceinline__ void ldsm4t(uint32_t* f, const void* p) {
    asm volatile("ldmatrix.sync.aligned.m8n8.x4.trans.shared.b16 {%0,%1,%2,%3}, [%4];\n"
                 : "=r"(f[0]), "=r"(f[1]), "=r"(f[2]), "=r"(f[3]) : "r"(sptr(p)));
}
__device__ __forceinline__ void ldsm4(uint32_t* f, const void* p) {
    asm volatile("ldmatrix.sync.aligned.m8n8.x4.shared.b16 {%0,%1,%2,%3}, [%4];\n"
                 : "=r"(f[0]), "=r"(f[1]), "=r"(f[2]), "=r"(f[3]) : "r"(sptr(p)));
}
__device__ __forceinline__ void mma16816(float* c, const uint32_t* a, uint32_t b0, uint32_t b1) {
    asm volatile(
        "mma.sync.aligned.m16n8k16.row.col.f32.f16.f16.f32 "
        "{%0,%1,%2,%3}, {%4,%5,%6,%7}, {%8,%9}, {%0,%1,%2,%3};\n"
        : "+f"(c[0]), "+f"(c[1]), "+f"(c[2]), "+f"(c[3])
        : "r"(a[0]), "r"(a[1]), "r"(a[2]), "r"(a[3]), "r"(b0), "r"(b1));
}
__device__ __forceinline__ void mma16816h(uint32_t* c, const uint32_t* a, uint32_t b0, uint32_t b1) {
    asm volatile(
        "mma.sync.aligned.m16n8k16.row.col.f16.f16.f16.f16 "
        "{%0,%1}, {%2,%3,%4,%5}, {%6,%7}, {%0,%1};\n"
        : "+r"(c[0]), "+r"(c[1])
        : "r"(a[0]), "r"(a[1]), "r"(a[2]), "r"(a[3]), "r"(b0), "r"(b1));
}

// ---------------- GroupNorm partials + weight conversion (fused launch) ----------------
__global__ void gn_conv_kernel(const float* __restrict__ x,
                               const float* __restrict__ qw, const float* __restrict__ pw) {
    if (blockIdx.x >= 256) {
        int i = (blockIdx.x - 256) * 256 + threadIdx.x;
        if (i < 3 * CC * CC) g_qw16[i] = __float2half(qw[i]);
        if (i < CC * CC)     g_pw16[i] = __float2half(pw[i]);
        return;
    }
    int ng = blockIdx.x >> 3, part = blockIdx.x & 7;
    const float4* xp = (const float4*)(x + (size_t)ng * GC * HWD);
    float s = 0.f, ss = 0.f;
    int i0 = part * 4096;
    for (int i = i0 + threadIdx.x; i < i0 + 4096; i += 256) {
        float4 v = xp[i];
        s  += v.x + v.y + v.z + v.w;
        ss += v.x * v.x + v.y * v.y + v.z * v.z + v.w * v.w;
    }
    #pragma unroll
    for (int off = 16; off; off >>= 1) {
        s  += __shfl_down_sync(0xffffffffu, s, off);
        ss += __shfl_down_sync(0xffffffffu, ss, off);
    }
    __shared__ float sh[16];
    int w = threadIdx.x >> 5;
    if ((threadIdx.x & 31) == 0) { sh[w] = s; sh[8 + w] = ss; }
    __syncthreads();
    if (threadIdx.x == 0) {
        float S = 0.f, SS = 0.f;
        #pragma unroll
        for (int i = 0; i < 8; i++) { S += sh[i]; SS += sh[8 + i]; }
        g_part[blockIdx.x * 2] = S; g_part[blockIdx.x * 2 + 1] = SS;
    }
}

// ---------------- fused GN + QKV GEMM (fp16 tensor core) ----------------
#define GA_ST 5120
#define GB_OFF (3 * GA_ST)
#define GB_ST 4352
#define QKV_SMEM ((GB_OFF + 2 * GB_ST) * 2)

__global__ __launch_bounds__(256, 2) void gemm_qkv16_kernel(
    const float* __restrict__ x,
    const float* __restrict__ nw, const float* __restrict__ nb_,
    const float* __restrict__ qkv_b)
{
    extern __shared__ __align__(16) __half GS[];
    __shared__ float sc[CC], bc[CC];
    const int n  = blockIdx.z;
    const int o0 = blockIdx.y * 128;
    const int j0 = blockIdx.x * 128;

    const int tid = threadIdx.x, w = tid >> 5, lane = tid & 31;
    const int wm = w >> 1, wn = w & 1;
    const int g = lane >> 2, t4 = lane & 3, mi = lane >> 3, r8 = lane & 7;
    const int la = lane & 15, ha = lane >> 4;

    {
        int c = tid;
        int ng = n * NGRP + c / GC;
        float s = 0.f, ss = 0.f;
        #pragma unroll
        for (int p = 0; p < 8; p++) {
            s  += g_part[(ng * 8 + p) * 2];
            ss += g_part[(ng * 8 + p) * 2 + 1];
        }
        const float invn = 1.0f / (float)(GC * HWD);
        float m  = s * invn;
        float rs = rsqrtf(ss * invn - m * m + EPSV);
        float scv = rs * nw[c];
        sc[c] = scv;
        bc[c] = nb_[c] - m * scv;
    }

    auto prefetchA = [&](int buf, int k0) {
        __half* Ab = GS + buf * GA_ST;
        #pragma unroll
        for (int i = 0; i < 2; i++) {
            int s = tid + 256 * i;
            int row = s >> 2, c8 = (s & 3) * 8;
            cp16(&Ab[row * 40 + c8], &g_qw16[(size_t)(o0 + row) * CC + k0 + c8]);
        }
        asm volatile("cp.async.commit_group;\n");
    };

    const float* xb = x + (size_t)n * CC * HWD;
    const int brow = tid >> 3;
    const int bj   = (tid & 7) * 16;
    uint32_t breg[8];
    auto loadB = [&](int k0) {
        float scv = sc[k0 + brow], bcv = bc[k0 + brow];
        const float* src = xb + (size_t)(k0 + brow) * HWD + j0 + bj;
        #pragma unroll
        for (int i = 0; i < 4; i++) {
            float4 v = *(const float4*)(src + 4 * i);
            breg[2 * i]     = pack2(v.x * scv + bcv, v.y * scv + bcv);
            breg[2 * i + 1] = pack2(v.z * scv + bcv, v.w * scv + bcv);
        }
    };
    auto stsB = [&](int buf) {
        __half* Bb = GS + GB_OFF + buf * GB_ST;
        *(uint4*)&Bb[brow * 136 + bj]     = *(uint4*)&breg[0];
        *(uint4*)&Bb[brow * 136 + bj + 8] = *(uint4*)&breg[4];
    };

    prefetchA(0, 0);
    prefetchA(1, 32);
    __syncthreads();
    loadB(0);

    float acc[2][8][4] = {};
    for (int c = 0; c < 8; c++) {
        stsB(c & 1);
        if (c < 7)  asm volatile("cp.async.wait_group 1;\n");
        else        asm volatile("cp.async.wait_group 0;\n");
        __syncthreads();
        if (c + 2 < 8) prefetchA((c + 2) % 3, (c + 2) * 32);
        if (c + 1 < 8) loadB((c + 1) * 32);

        __half* Ab = GS + (c % 3) * GA_ST;
        __half* Bb = GS + GB_OFF + (c & 1) * GB_ST;
        #pragma unroll
        for (int ks = 0; ks < 2; ks++) {
            uint32_t a[2][4];
            #pragma unroll
            for (int mt = 0; mt < 2; mt++)
                ldsm4(a[mt], &Ab[(wm * 32 + mt * 16 + la) * 40 + ks * 16 + ha * 8]);
            #pragma unroll
            for (int nb = 0; nb < 4; nb++) {
                uint32_t b[4];
                ldsm4t(b, &Bb[(ks * 16 + (mi & 1) * 8 + r8) * 136 + wn * 64 + nb * 16 + (mi >> 1) * 8]);
                #pragma unroll
                for (int mt = 0; mt < 2; mt++) {
                    mma16816(acc[mt][2 * nb],     a[mt], b[0], b[1]);
                    mma16816(acc[mt][2 * nb + 1], a[mt], b[2], b[3]);
                }
            }
        }
        __syncthreads();
    }

    const int part = o0 >> 8;
    __half* dst = (part == 0) ? g_q16 : ((part == 1) ? g_k16 : g_v16);
    const float scale = (part == 0) ? (0.125f * LOG2E) : 1.0f;
    #pragma unroll
    for (int mt = 0; mt < 2; mt++) {
        int o_lo = o0 + wm * 32 + mt * 16 + g;
        float b_lo = qkv_b[o_lo], b_hi = qkv_b[o_lo + 8];
        int c_lo = o_lo & 255;
        #pragma unroll
        for (int nt = 0; nt < 8; nt++) {
            int j = j0 + wn * 64 + nt * 8 + 2 * t4;
            *(uint32_t*)&dst[((size_t)n * CC + c_lo) * HWD + j] =
                pack2((acc[mt][nt][0] + b_lo) * scale, (acc[mt][nt][1] + b_lo) * scale);
            *(uint32_t*)&dst[((size_t)n * CC + c_lo + 8) * HWD + j] =
                pack2((acc[mt][nt][2] + b_hi) * scale, (acc[mt][nt][3] + b_hi) * scale);
        }
    }
}

// ---------------- proj GEMM fused with split-K reduce + residual + mask ----------------
// B[k][j] = (O0[k][j] + O1[k][j]) / (l0[h][j] + l1[h][j]), built on the fly.
__global__ __launch_bounds__(256, 2) void gemm_proj16_kernel(
    const float* __restrict__ x, const float* __restrict__ mask,
    const float* __restrict__ pb, float* __restrict__ out)
{
    extern __shared__ __align__(16) __half GS[];
    __shared__ float linv[NH * 128];
    const int n  = blockIdx.z;
    const int j0 = blockIdx.x * 128;

    if (blockIdx.y == 2) {   // mask copy tail
        if (threadIdx.x < 128) {
            float* mout = out + (size_t)NB * CC * HWD;
            int idx = n * HWD + j0 + threadIdx.x;
            mout[idx] = mask[idx];
        }
        return;
    }
    const int o0 = blockIdx.y * 128;

    const int tid = threadIdx.x, w = tid >> 5, lane = tid & 31;
    const int wm = w >> 1, wn = w & 1;
    const int g = lane >> 2, t4 = lane & 3, mi = lane >> 3, r8 = lane & 7;
    const int la = lane & 15, ha = lane >> 4;

    // 1/(l0+l1) for the 4 heads x 128 q of this CTA
    #pragma unroll
    for (int i = 0; i < 2; i++) {
        int idx = tid + 256 * i;     // 512 entries
        int hh = idx >> 7, q = idx & 127;
        size_t off = (size_t)(n * NH + hh) * HWD + j0 + q;
        linv[idx] = 1.0f / (g_pl[off] + g_pl[(size_t)NB * NH * HWD + off]);
    }

    auto prefetchA = [&](int buf, int k0) {
        __half* Ab = GS + buf * GA_ST;
        #pragma unroll
        for (int i = 0; i < 2; i++) {
            int s = tid + 256 * i;
            int row = s >> 2, c8 = (s & 3) * 8;
            cp16(&Ab[row * 40 + c8], &g_pw16[(size_t)(o0 + row) * CC + k0 + c8]);
        }
        asm volatile("cp.async.commit_group;\n");
    };

    const int brow = tid >> 3;
    const int bj   = (tid & 7) * 16;
    uint32_t breg[8];
    auto loadB = [&](int k0) {
        int c = k0 + brow;
        int hc = c >> 6;
        size_t off = ((size_t)n * CC + c) * HWD + j0 + bj;
        const float* lv = &linv[hc * 128 + bj];
        uint4 u0 = *(const uint4*)&g_po16[off];
        uint4 u1 = *(const uint4*)&g_po16[SPLIT_OFF + off];
        uint4 v0 = *(const uint4*)&g_po16[off + 8];
        uint4 v1 = *(const uint4*)&g_po16[SPLIT_OFF + off + 8];
        const uint32_t* a0 = (const uint32_t*)&u0;
        const uint32_t* a1 = (const uint32_t*)&u1;
        const uint32_t* b0 = (const uint32_t*)&v0;
        const uint32_t* b1 = (const uint32_t*)&v1;
        #pragma unroll
        for (int i = 0; i < 4; i++) {
            __half2 s0 = u2h(a0[i]), s1 = u2h(a1[i]);
            breg[i] = pack2((__low2float(s0) + __low2float(s1)) * lv[2 * i],
                            (__high2float(s0) + __high2float(s1)) * lv[2 * i + 1]);
            __half2 t0 = u2h(b0[i]), t1 = u2h(b1[i]);
            breg[4 + i] = pack2((__low2float(t0) + __low2float(t1)) * lv[8 + 2 * i],
                                (__high2float(t0) + __high2float(t1)) * lv[8 + 2 * i + 1]);
        }
    };
    auto stsB = [&](int buf) {
        __half* Bb = GS + GB_OFF + buf * GB_ST;
        *(uint4*)&Bb[brow * 136 + bj]     = *(uint4*)&breg[0];
        *(uint4*)&Bb[brow * 136 + bj + 8] = *(uint4*)&breg[4];
    };

    prefetchA(0, 0);
    prefetchA(1, 32);
    __syncthreads();     // linv ready
    loadB(0);

    float acc[2][8][4] = {};
    for (int c = 0; c < 8; c++) {
        stsB(c & 1);
        if (c < 7)  asm volatile("cp.async.wait_group 1;\n");
        else        asm volatile("cp.async.wait_group 0;\n");
        __syncthreads();
        if (c + 2 < 8) prefetchA((c + 2) % 3, (c + 2) * 32);
        if (c + 1 < 8) loadB((c + 1) * 32);

        __half* Ab = GS + (c % 3) * GA_ST;
        __half* Bb = GS + GB_OFF + (c & 1) * GB_ST;
        #pragma unroll
        for (int ks = 0; ks < 2; ks++) {
            uint32_t a[2][4];
            #pragma unroll
            for (int mt = 0; mt < 2; mt++)
                ldsm4(a[mt], &Ab[(wm * 32 + mt * 16 + la) * 40 + ks * 16 + ha * 8]);
            #pragma unroll
            for (int nb = 0; nb < 4; nb++) {
                uint32_t b[4];
                ldsm4t(b, &Bb[(ks * 16 + (mi & 1) * 8 + r8) * 136 + wn * 64 + nb * 16 + (mi >> 1) * 8]);
                #pragma unroll
                for (int mt = 0; mt < 2; mt++) {
                    mma16816(acc[mt][2 * nb],     a[mt], b[0], b[1]);
                    mma16816(acc[mt][2 * nb + 1], a[mt], b[2], b[3]);
                }
            }
        }
        __syncthreads();
    }

    #pragma unroll
    for (int mt = 0; mt < 2; mt++) {
        int o_lo = o0 + wm * 32 + mt * 16 + g;
        float b_lo = pb[o_lo], b_hi = pb[o_lo + 8];
        #pragma unroll
        for (int nt = 0; nt < 8; nt++) {
            int j = j0 + wn * 64 + nt * 8 + 2 * t4;
            float2 mv = *(const float2*)&mask[(size_t)n * HWD + j];
            size_t off = ((size_t)n * CC + o_lo) * HWD + j;
            float2 xv = *(const float2*)&x[off];
            float2 r;
            r.x = (xv.x + acc[mt][nt][0] + b_lo) * mv.x;
            r.y = (xv.y + acc[mt][nt][1] + b_lo) * mv.y;
            *(float2*)&out[off] = r;
            size_t off2 = off + 8 * HWD;
            float2 xv2 = *(const float2*)&x[off2];
            float2 r2;
            r2.x = (xv2.x + acc[mt][nt][2] + b_hi) * mv.x;
            r2.y = (xv2.y + acc[mt][nt][3] + b_hi) * mv.y;
            *(float2*)&out[off2] = r2;
        }
    }
}

// ---------------- Flash attention: split-K x2, fixed-bias softmax, f16 partials ----------------
#define KP 72
#define QP 136
#define BIAS_H2 0xC800C800u   // f16x2 {-8, -8}
__global__ __launch_bounds__(128, 3) void attn_kernel() {
    __shared__ __align__(16) __half SMh[18432];   // 36864 B
    const int n = blockIdx.y >> 2, h = blockIdx.y & 3;
    const int q0 = blockIdx.x * 128;
    const int split = blockIdx.z;
    const int c0 = split * CHUNKS_PER_SPLIT;
    const size_t base = (size_t)(n * CC + h * HD) * HWD;
    const __half* qg = g_q16 + base;
    const __half* kg = g_k16 + base;
    const __half* vg = g_v16 + base;

    const int tid = threadIdx.x, w = tid >> 5, lane = tid & 31;
    const int g = lane >> 2, t4 = lane & 3, mi = lane >> 3, r8 = lane & 7;

    #pragma unroll
    for (int i = 0; i < 8; i++) {
        int s = tid + 128 * i;
        int row = s >> 4, c8 = (s & 15) * 8;
        *(uint4*)&SMh[row * QP + c8] = *(const uint4*)&qg[(size_t)row * HWD + q0 + c8];
    }
    __syncthreads();
    uint32_t aq[2][4][4];
    #pragma unroll
    for (int mt = 0; mt < 2; mt++)
        #pragma unroll
        for (int kt = 0; kt < 4; kt++)
            ldsm4t(aq[mt][kt],
                   &SMh[(kt * 16 + (mi >> 1) * 8 + r8) * QP + w * 32 + mt * 16 + (mi & 1) * 8]);
    __syncthreads();

    auto prefetch = [&](int buf, int c) {
        int jc = c * 64;
        __half* Kb = &SMh[buf * 4608];
        __half* Vb = &SMh[9216 + buf * 4608];
        #pragma unroll
        for (int i = 0; i < 4; i++) {
            int s = tid + 128 * i;
            int row = s >> 3, c8 = (s & 7) * 8;
            cp16(&Kb[row * KP + c8], &kg[(size_t)row * HWD + jc + c8]);
            cp16(&Vb[row * KP + c8], &vg[(size_t)row * HWD + jc + c8]);
        }
        asm volatile("cp.async.commit_group;\n");
    };

    float o_[2][8][4] = {};
    float l[2][2] = {};

    prefetch(0, c0);
    for (int c = c0; c < c0 + CHUNKS_PER_SPLIT; c++) {
        int buf = c & 1;
        if (c + 1 < c0 + CHUNKS_PER_SPLIT) { prefetch(buf ^ 1, c + 1); asm volatile("cp.async.wait_group 1;\n"); }
        else                               { asm volatile("cp.async.wait_group 0;\n"); }
        __syncthreads();
        const __half* Kb = &SMh[buf * 4608];
        const __half* Vb = &SMh[9216 + buf * 4608];

        // S = Q K^T + (-8), f16 accumulators
        uint32_t s[2][8][2];
        #pragma unroll
        for (int mt = 0; mt < 2; mt++)
            #pragma unroll
            for (int nt = 0; nt < 8; nt++) { s[mt][nt][0] = BIAS_H2; s[mt][nt][1] = BIAS_H2; }
        #pragma unroll
        for (int kt = 0; kt < 4; kt++) {
            #pragma unroll
            for (int ntp = 0; ntp < 4; ntp++) {
                uint32_t b[4];
                ldsm4t(b, &Kb[(kt * 16 + (mi & 1) * 8 + r8) * KP + ntp * 16 + (mi >> 1) * 8]);
                #pragma unroll
                for (int mt = 0; mt < 2; mt++) {
                    mma16816h(s[mt][2 * ntp],     aq[mt][kt], b[0], b[1]);
                    mma16816h(s[mt][2 * ntp + 1], aq[mt][kt], b[2], b[3]);
                }
            }
        }

        // p = exp2(s - 8) in place; accumulate row sums
        #pragma unroll
        for (int mt = 0; mt < 2; mt++) {
            __half2 hs0 = __floats2half2_rn(0.f, 0.f), hs1 = hs0;
            #pragma unroll
            for (int nt = 0; nt < 8; nt++) {
                uint32_t p0 = h2ex2(s[mt][nt][0]);
                uint32_t p1 = h2ex2(s[mt][nt][1]);
                s[mt][nt][0] = p0; s[mt][nt][1] = p1;
                hs0 = __hadd2(hs0, u2h(p0));
                hs1 = __hadd2(hs1, u2h(p1));
            }
            l[mt][0] += __low2float(hs0) + __high2float(hs0);
            l[mt][1] += __low2float(hs1) + __high2float(hs1);
        }

        // O += P V   (P aliases S)
        #pragma unroll
        for (int kt = 0; kt < 4; kt++) {
            #pragma unroll
            for (int ntp = 0; ntp < 4; ntp++) {
                uint32_t b[4];
                ldsm4(b, &Vb[(ntp * 16 + (mi >> 1) * 8 + r8) * KP + kt * 16 + (mi & 1) * 8]);
                #pragma unroll
                for (int mt = 0; mt < 2; mt++) {
                    uint32_t ap[4] = { s[mt][2 * kt][0], s[mt][2 * kt][1],
                                       s[mt][2 * kt + 1][0], s[mt][2 * kt + 1][1] };
                    mma16816(o_[mt][2 * ntp],     ap, b[0], b[1]);
                    mma16816(o_[mt][2 * ntp + 1], ap, b[2], b[3]);
                }
            }
        }
        __syncthreads();
    }

    // partial epilogue: quad row sums for l, write l (f32) + un-normalized O (f16)
    #pragma unroll
    for (int mt = 0; mt < 2; mt++)
        #pragma unroll
        for (int hh = 0; hh < 2; hh++) {
            l[mt][hh] += __shfl_xor_sync(0xffffffffu, l[mt][hh], 1);
            l[mt][hh] += __shfl_xor_sync(0xffffffffu, l[mt][hh], 2);
        }
    float* pl = g_pl + (size_t)split * NB * NH * HWD + (size_t)(n * NH + h) * HWD + q0;
    if (t4 == 0) {
        #pragma unroll
        for (int mt = 0; mt < 2; mt++) {
            int qr = w * 32 + mt * 16 + g;
            pl[qr]     = l[mt][0];
            pl[qr + 8] = l[mt][1];
        }
    }

    __syncthreads();
    #pragma unroll
    for (int mt = 0; mt < 2; mt++) {
        int qr = w * 32 + mt * 16 + g;
        #pragma unroll
        for (int nt = 0; nt < 8; nt++) {
            int d0 = nt * 8 + 2 * t4;
            *(uint32_t*)&SMh[qr * KP + d0]       = pack2(o_[mt][nt][0], o_[mt][nt][1]);
            *(uint32_t*)&SMh[(qr + 8) * KP + d0] = pack2(o_[mt][nt][2], o_[mt][nt][3]);
        }
    }
    __syncthreads();
    __half* po = g_po16 + (size_t)split * SPLIT_OFF + base;
    #pragma unroll
    for (int i = 0; i < 32; i++) {
        int f = tid + 128 * i;
        int qp = f & 63, d = f >> 6;
        __half2 hv = __halves2half2(SMh[(2 * qp) * KP + d], SMh[(2 * qp + 1) * KP + d]);
        *(uint32_t*)&po[(size_t)d * HWD + q0 + 2 * qp] = *(uint32_t*)&hv;
    }
}

// ---------------------------------------------------------------------------
extern "C" void kernel_launch(void* const* d_in, const int* in_sizes, int n_in,
                              void* d_out, int out_size) {
    const float* x      = (const float*)d_in[0];
    const float* mask   = (const float*)d_in[1];
    const float* norm_w = (const float*)d_in[2];
    const float* norm_b = (const float*)d_in[3];
    const float* qkv_w  = (const float*)d_in[4];
    const float* qkv_b  = (const float*)d_in[5];
    const float* proj_w = (const float*)d_in[6];
    const float* proj_b = (const float*)d_in[7];
    float* out = (float*)d_out;

    cudaFuncSetAttribute(gemm_qkv16_kernel,  cudaFuncAttributeMaxDynamicSharedMemorySize, QKV_SMEM);
    cudaFuncSetAttribute(gemm_proj16_kernel, cudaFuncAttributeMaxDynamicSharedMemorySize, QKV_SMEM);

    gn_conv_kernel<<<256 + 1024, 256>>>(x, qkv_w, proj_w);
    gemm_qkv16_kernel<<<dim3(HWD / 128, (3 * CC) / 128, NB), 256, QKV_SMEM>>>(x, norm_w, norm_b, qkv_b);
    attn_kernel<<<dim3(HWD / 128, NB * NH, NSPLIT), 128>>>();
    int ny = (out_size >= NB * CC * HWD + NB * HWD) ? 3 : 2;
    gemm_proj16_kernel<<<dim3(HWD / 128, ny, NB), 256, QKV_SMEM>>>(x, mask, proj_b, out);
}

// round 14
// speedup vs baseline: 1.0339x; 1.0040x over previous
#include <cuda_runtime.h>
#include <cuda_fp16.h>
#include <math.h>
#include <stdint.h>

#define NB 4
#define CC 256
#define HWD 4096
#define NH 4
#define HD 64
#define NGRP 8
#define GC 32
#define EPSV 1e-5f
#define LOG2E 1.44269504088896340736f
#define NSPLIT 2
#define SPLIT_OFF (NB * CC * HWD)
#define CHUNKS_PER_SPLIT (64 / NSPLIT)

// ---- scratch (allocation-free) ----
__device__ __half g_q16[NB * CC * HWD];
__device__ __half g_k16[NB * CC * HWD];
__device__ __half g_v16[NB * CC * HWD];
__device__ __half g_ao16[NB * CC * HWD];
__device__ __half g_qw16[3 * CC * CC];
__device__ __half g_pw16[CC * CC];
__device__ float  g_part[256 * 2];
__device__ __half g_po16[NSPLIT * NB * CC * HWD];   // partial O (f16, un-normalized)
__device__ float  g_pl[NSPLIT * NB * NH * HWD];     // partial l (f32)

// ---------------- helpers ----------------
__device__ __forceinline__ uint32_t h2ex2(uint32_t x) {
    uint32_t y; asm("ex2.approx.f16x2 %0, %1;" : "=r"(y) : "r"(x)); return y;
}
__device__ __forceinline__ uint32_t pack2(float a, float b) {
    __half2 h = __floats2half2_rn(a, b);
    return *reinterpret_cast<uint32_t*>(&h);
}
__device__ __forceinline__ __half2 u2h(uint32_t u) { return *reinterpret_cast<__half2*>(&u); }
__device__ __forceinline__ uint32_t sptr(const void* p) {
    return (uint32_t)__cvta_generic_to_shared(p);
}
__device__ __forceinline__ void cp16(void* dst, const void* src) {
    asm volatile("cp.async.cg.shared.global [%0], [%1], 16;\n"
                 :: "r"(sptr(dst)), "l"(src));
}
__device__ __forceinline__ void ldsm4t(uint32_t* f, const void* p) {
    asm volatile("ldmatrix.sync.aligned.m8n8.x4.trans.shared.b16 {%0,%1,%2,%3}, [%4];\n"
                 : "=r"(f[0]), "=r"(f[1]), "=r"(f[2]), "=r"(f[3]) : "r"(sptr(p)));
}
__device__ __forceinline__ void ldsm4(uint32_t* f, const void* p) {
    asm volatile("ldmatrix.sync.aligned.m8n8.x4.shared.b16 {%0,%1,%2,%3}, [%4];\n"
                 : "=r"(f[0]), "=r"(f[1]), "=r"(f[2]), "=r"(f[3]) : "r"(sptr(p)));
}
__device__ __forceinline__ void mma16816(float* c, const uint32_t* a, uint32_t b0, uint32_t b1) {
    asm volatile(
        "mma.sync.aligned.m16n8k16.row.col.f32.f16.f16.f32 "
        "{%0,%1,%2,%3}, {%4,%5,%6,%7}, {%8,%9}, {%0,%1,%2,%3};\n"
        : "+f"(c[0]), "+f"(c[1]), "+f"(c[2]), "+f"(c[3])
        : "r"(a[0]), "r"(a[1]), "r"(a[2]), "r"(a[3]), "r"(b0), "r"(b1));
}
__device__ __forceinline__ void mma16816h(uint32_t* c, const uint32_t* a, uint32_t b0, uint32_t b1) {
    asm volatile(
        "mma.sync.aligned.m16n8k16.row.col.f16.f16.f16.f16 "
        "{%0,%1}, {%2,%3,%4,%5}, {%6,%7}, {%0,%1};\n"
        : "+r"(c[0]), "+r"(c[1])
        : "r"(a[0]), "r"(a[1]), "r"(a[2]), "r"(a[3]), "r"(b0), "r"(b1));
}

// ---------------- GroupNorm partials + weight conversion (fused launch) ----------------
__global__ void gn_conv_kernel(const float* __restrict__ x,
                               const float* __restrict__ qw, const float* __restrict__ pw) {
    if (blockIdx.x >= 256) {
        int i = (blockIdx.x - 256) * 256 + threadIdx.x;
        if (i < 3 * CC * CC) g_qw16[i] = __float2half(qw[i]);
        if (i < CC * CC)     g_pw16[i] = __float2half(pw[i]);
        return;
    }
    int ng = blockIdx.x >> 3, part = blockIdx.x & 7;
    const float4* xp = (const float4*)(x + (size_t)ng * GC * HWD);
    float s = 0.f, ss = 0.f;
    int i0 = part * 4096;
    for (int i = i0 + threadIdx.x; i < i0 + 4096; i += 256) {
        float4 v = xp[i];
        s  += v.x + v.y + v.z + v.w;
        ss += v.x * v.x + v.y * v.y + v.z * v.z + v.w * v.w;
    }
    #pragma unroll
    for (int off = 16; off; off >>= 1) {
        s  += __shfl_down_sync(0xffffffffu, s, off);
        ss += __shfl_down_sync(0xffffffffu, ss, off);
    }
    __shared__ float sh[16];
    int w = threadIdx.x >> 5;
    if ((threadIdx.x & 31) == 0) { sh[w] = s; sh[8 + w] = ss; }
    __syncthreads();
    if (threadIdx.x == 0) {
        float S = 0.f, SS = 0.f;
        #pragma unroll
        for (int i = 0; i < 8; i++) { S += sh[i]; SS += sh[8 + i]; }
        g_part[blockIdx.x * 2] = S; g_part[blockIdx.x * 2 + 1] = SS;
    }
}

// ---------------- fused GN + QKV GEMM (fp16 tensor core) ----------------
#define GA_ST 5120
#define GB_OFF (3 * GA_ST)
#define GB_ST 4352
#define QKV_SMEM ((GB_OFF + 2 * GB_ST) * 2)

__global__ __launch_bounds__(256, 2) void gemm_qkv16_kernel(
    const float* __restrict__ x,
    const float* __restrict__ nw, const float* __restrict__ nb_,
    const float* __restrict__ qkv_b)
{
    extern __shared__ __align__(16) __half GS[];
    __shared__ float sc[CC], bc[CC];
    const int n  = blockIdx.z;
    const int o0 = blockIdx.y * 128;
    const int j0 = blockIdx.x * 128;

    const int tid = threadIdx.x, w = tid >> 5, lane = tid & 31;
    const int wm = w >> 1, wn = w & 1;
    const int g = lane >> 2, t4 = lane & 3, mi = lane >> 3, r8 = lane & 7;
    const int la = lane & 15, ha = lane >> 4;

    {
        int c = tid;
        int ng = n * NGRP + c / GC;
        float s = 0.f, ss = 0.f;
        #pragma unroll
        for (int p = 0; p < 8; p++) {
            s  += g_part[(ng * 8 + p) * 2];
            ss += g_part[(ng * 8 + p) * 2 + 1];
        }
        const float invn = 1.0f / (float)(GC * HWD);
        float m  = s * invn;
        float rs = rsqrtf(ss * invn - m * m + EPSV);
        float scv = rs * nw[c];
        sc[c] = scv;
        bc[c] = nb_[c] - m * scv;
    }

    auto prefetchA = [&](int buf, int k0) {
        __half* Ab = GS + buf * GA_ST;
        #pragma unroll
        for (int i = 0; i < 2; i++) {
            int s = tid + 256 * i;
            int row = s >> 2, c8 = (s & 3) * 8;
            cp16(&Ab[row * 40 + c8], &g_qw16[(size_t)(o0 + row) * CC + k0 + c8]);
        }
        asm volatile("cp.async.commit_group;\n");
    };

    const float* xb = x + (size_t)n * CC * HWD;
    const int brow = tid >> 3;
    const int bj   = (tid & 7) * 16;
    uint32_t breg[8];
    auto loadB = [&](int k0) {
        float scv = sc[k0 + brow], bcv = bc[k0 + brow];
        const float* src = xb + (size_t)(k0 + brow) * HWD + j0 + bj;
        #pragma unroll
        for (int i = 0; i < 4; i++) {
            float4 v = *(const float4*)(src + 4 * i);
            breg[2 * i]     = pack2(v.x * scv + bcv, v.y * scv + bcv);
            breg[2 * i + 1] = pack2(v.z * scv + bcv, v.w * scv + bcv);
        }
    };
    auto stsB = [&](int buf) {
        __half* Bb = GS + GB_OFF + buf * GB_ST;
        *(uint4*)&Bb[brow * 136 + bj]     = *(uint4*)&breg[0];
        *(uint4*)&Bb[brow * 136 + bj + 8] = *(uint4*)&breg[4];
    };

    prefetchA(0, 0);
    prefetchA(1, 32);
    __syncthreads();
    loadB(0);

    float acc[2][8][4] = {};
    for (int c = 0; c < 8; c++) {
        stsB(c & 1);
        if (c < 7)  asm volatile("cp.async.wait_group 1;\n");
        else        asm volatile("cp.async.wait_group 0;\n");
        __syncthreads();
        if (c + 2 < 8) prefetchA((c + 2) % 3, (c + 2) * 32);
        if (c + 1 < 8) loadB((c + 1) * 32);

        __half* Ab = GS + (c % 3) * GA_ST;
        __half* Bb = GS + GB_OFF + (c & 1) * GB_ST;
        #pragma unroll
        for (int ks = 0; ks < 2; ks++) {
            uint32_t a[2][4];
            #pragma unroll
            for (int mt = 0; mt < 2; mt++)
                ldsm4(a[mt], &Ab[(wm * 32 + mt * 16 + la) * 40 + ks * 16 + ha * 8]);
            #pragma unroll
            for (int nb = 0; nb < 4; nb++) {
                uint32_t b[4];
                ldsm4t(b, &Bb[(ks * 16 + (mi & 1) * 8 + r8) * 136 + wn * 64 + nb * 16 + (mi >> 1) * 8]);
                #pragma unroll
                for (int mt = 0; mt < 2; mt++) {
                    mma16816(acc[mt][2 * nb],     a[mt], b[0], b[1]);
                    mma16816(acc[mt][2 * nb + 1], a[mt], b[2], b[3]);
                }
            }
        }
        __syncthreads();
    }

    const int part = o0 >> 8;
    __half* dst = (part == 0) ? g_q16 : ((part == 1) ? g_k16 : g_v16);
    const float scale = (part == 0) ? (0.125f * LOG2E) : 1.0f;
    #pragma unroll
    for (int mt = 0; mt < 2; mt++) {
        int o_lo = o0 + wm * 32 + mt * 16 + g;
        float b_lo = qkv_b[o_lo], b_hi = qkv_b[o_lo + 8];
        int c_lo = o_lo & 255;
        #pragma unroll
        for (int nt = 0; nt < 8; nt++) {
            int j = j0 + wn * 64 + nt * 8 + 2 * t4;
            *(uint32_t*)&dst[((size_t)n * CC + c_lo) * HWD + j] =
                pack2((acc[mt][nt][0] + b_lo) * scale, (acc[mt][nt][1] + b_lo) * scale);
            *(uint32_t*)&dst[((size_t)n * CC + c_lo + 8) * HWD + j] =
                pack2((acc[mt][nt][2] + b_hi) * scale, (acc[mt][nt][3] + b_hi) * scale);
        }
    }
}

// ---------------- proj GEMM + residual + mask (cp.async B from ao16) ----------------
#define PROJ_SMEM ((GB_OFF + 3 * GB_ST) * 2)

__global__ __launch_bounds__(256, 2) void gemm_proj16_kernel(
    const float* __restrict__ x, const float* __restrict__ mask,
    const float* __restrict__ pb, float* __restrict__ out)
{
    extern __shared__ __align__(16) __half GS[];
    const int n  = blockIdx.z;
    const int j0 = blockIdx.x * 128;

    if (blockIdx.y == 2) {   // mask copy tail
        if (threadIdx.x < 128) {
            float* mout = out + (size_t)NB * CC * HWD;
            int idx = n * HWD + j0 + threadIdx.x;
            mout[idx] = mask[idx];
        }
        return;
    }
    const int o0 = blockIdx.y * 128;

    const int tid = threadIdx.x, w = tid >> 5, lane = tid & 31;
    const int wm = w >> 1, wn = w & 1;
    const int g = lane >> 2, t4 = lane & 3, mi = lane >> 3, r8 = lane & 7;
    const int la = lane & 15, ha = lane >> 4;
    const __half* Bsrc = g_ao16 + (size_t)n * CC * HWD;

    auto prefetch = [&](int buf, int k0) {
        __half* Ab = GS + buf * GA_ST;
        __half* Bb = GS + GB_OFF + buf * GB_ST;
        #pragma unroll
        for (int i = 0; i < 2; i++) {
            int s = tid + 256 * i;
            int row = s >> 2, c8 = (s & 3) * 8;
            cp16(&Ab[row * 40 + c8], &g_pw16[(size_t)(o0 + row) * CC + k0 + c8]);
        }
        #pragma unroll
        for (int i = 0; i < 2; i++) {
            int s = tid + 256 * i;
            int row = s >> 4, c8 = (s & 15) * 8;
            cp16(&Bb[row * 136 + c8], &Bsrc[(size_t)(k0 + row) * HWD + j0 + c8]);
        }
        asm volatile("cp.async.commit_group;\n");
    };

    float acc[2][8][4] = {};
    prefetch(0, 0);
    prefetch(1, 32);
    for (int c = 0; c < 8; c++) {
        if (c < 7) asm volatile("cp.async.wait_group 1;\n");
        else       asm volatile("cp.async.wait_group 0;\n");
        __syncthreads();
        if (c + 2 < 8) prefetch((c + 2) % 3, (c + 2) * 32);
        int buf = c % 3;
        __half* Ab = GS + buf * GA_ST;
        __half* Bb = GS + GB_OFF + buf * GB_ST;
        #pragma unroll
        for (int ks = 0; ks < 2; ks++) {
            uint32_t a[2][4];
            #pragma unroll
            for (int mt = 0; mt < 2; mt++)
                ldsm4(a[mt], &Ab[(wm * 32 + mt * 16 + la) * 40 + ks * 16 + ha * 8]);
            #pragma unroll
            for (int nb = 0; nb < 4; nb++) {
                uint32_t b[4];
                ldsm4t(b, &Bb[(ks * 16 + (mi & 1) * 8 + r8) * 136 + wn * 64 + nb * 16 + (mi >> 1) * 8]);
                #pragma unroll
                for (int mt = 0; mt < 2; mt++) {
                    mma16816(acc[mt][2 * nb],     a[mt], b[0], b[1]);
                    mma16816(acc[mt][2 * nb + 1], a[mt], b[2], b[3]);
                }
            }
        }
    }

    #pragma unroll
    for (int mt = 0; mt < 2; mt++) {
        int o_lo = o0 + wm * 32 + mt * 16 + g;
        float b_lo = pb[o_lo], b_hi = pb[o_lo + 8];
        #pragma unroll
        for (int nt = 0; nt < 8; nt++) {
            int j = j0 + wn * 64 + nt * 8 + 2 * t4;
            float2 mv = *(const float2*)&mask[(size_t)n * HWD + j];
            size_t off = ((size_t)n * CC + o_lo) * HWD + j;
            float2 xv = *(const float2*)&x[off];
            float2 r;
            r.x = (xv.x + acc[mt][nt][0] + b_lo) * mv.x;
            r.y = (xv.y + acc[mt][nt][1] + b_lo) * mv.y;
            *(float2*)&out[off] = r;
            size_t off2 = off + 8 * HWD;
            float2 xv2 = *(const float2*)&x[off2];
            float2 r2;
            r2.x = (xv2.x + acc[mt][nt][2] + b_hi) * mv.x;
            r2.y = (xv2.y + acc[mt][nt][3] + b_hi) * mv.y;
            *(float2*)&out[off2] = r2;
        }
    }
}

// ---------------- Flash attention: split-K x2, fixed-bias softmax, f16 partials ----------------
#define KP 72
#define QP 136
#define BIAS_H2 0xC800C800u   // f16x2 {-8, -8}
__global__ __launch_bounds__(128, 3) void attn_kernel() {
    __shared__ __align__(16) __half SMh[18432];   // 36864 B
    const int n = blockIdx.y >> 2, h = blockIdx.y & 3;
    const int q0 = blockIdx.x * 128;
    const int split = blockIdx.z;
    const int c0 = split * CHUNKS_PER_SPLIT;
    const size_t base = (size_t)(n * CC + h * HD) * HWD;
    const __half* qg = g_q16 + base;
    const __half* kg = g_k16 + base;
    const __half* vg = g_v16 + base;

    const int tid = threadIdx.x, w = tid >> 5, lane = tid & 31;
    const int g = lane >> 2, t4 = lane & 3, mi = lane >> 3, r8 = lane & 7;

    #pragma unroll
    for (int i = 0; i < 8; i++) {
        int s = tid + 128 * i;
        int row = s >> 4, c8 = (s & 15) * 8;
        *(uint4*)&SMh[row * QP + c8] = *(const uint4*)&qg[(size_t)row * HWD + q0 + c8];
    }
    __syncthreads();
    uint32_t aq[2][4][4];
    #pragma unroll
    for (int mt = 0; mt < 2; mt++)
        #pragma unroll
        for (int kt = 0; kt < 4; kt++)
            ldsm4t(aq[mt][kt],
                   &SMh[(kt * 16 + (mi >> 1) * 8 + r8) * QP + w * 32 + mt * 16 + (mi & 1) * 8]);
    __syncthreads();

    auto prefetch = [&](int buf, int c) {
        int jc = c * 64;
        __half* Kb = &SMh[buf * 4608];
        __half* Vb = &SMh[9216 + buf * 4608];
        #pragma unroll
        for (int i = 0; i < 4; i++) {
            int s = tid + 128 * i;
            int row = s >> 3, c8 = (s & 7) * 8;
            cp16(&Kb[row * KP + c8], &kg[(size_t)row * HWD + jc + c8]);
            cp16(&Vb[row * KP + c8], &vg[(size_t)row * HWD + jc + c8]);
        }
        asm volatile("cp.async.commit_group;\n");
    };

    float o_[2][8][4] = {};
    float l[2][2] = {};

    prefetch(0, c0);
    for (int c = c0; c < c0 + CHUNKS_PER_SPLIT; c++) {
        int buf = c & 1;
        if (c + 1 < c0 + CHUNKS_PER_SPLIT) { prefetch(buf ^ 1, c + 1); asm volatile("cp.async.wait_group 1;\n"); }
        else                               { asm volatile("cp.async.wait_group 0;\n"); }
        __syncthreads();
        const __half* Kb = &SMh[buf * 4608];
        const __half* Vb = &SMh[9216 + buf * 4608];

        // S = Q K^T + (-8), f16 accumulators
        uint32_t s[2][8][2];
        #pragma unroll
        for (int mt = 0; mt < 2; mt++)
            #pragma unroll
            for (int nt = 0; nt < 8; nt++) { s[mt][nt][0] = BIAS_H2; s[mt][nt][1] = BIAS_H2; }
        #pragma unroll
        for (int kt = 0; kt < 4; kt++) {
            #pragma unroll
            for (int ntp = 0; ntp < 4; ntp++) {
                uint32_t b[4];
                ldsm4t(b, &Kb[(kt * 16 + (mi & 1) * 8 + r8) * KP + ntp * 16 + (mi >> 1) * 8]);
                #pragma unroll
                for (int mt = 0; mt < 2; mt++) {
                    mma16816h(s[mt][2 * ntp],     aq[mt][kt], b[0], b[1]);
                    mma16816h(s[mt][2 * ntp + 1], aq[mt][kt], b[2], b[3]);
                }
            }
        }

        // p = exp2(s - 8) in place; accumulate row sums
        #pragma unroll
        for (int mt = 0; mt < 2; mt++) {
            __half2 hs0 = __floats2half2_rn(0.f, 0.f), hs1 = hs0;
            #pragma unroll
            for (int nt = 0; nt < 8; nt++) {
                uint32_t p0 = h2ex2(s[mt][nt][0]);
                uint32_t p1 = h2ex2(s[mt][nt][1]);
                s[mt][nt][0] = p0; s[mt][nt][1] = p1;
                hs0 = __hadd2(hs0, u2h(p0));
                hs1 = __hadd2(hs1, u2h(p1));
            }
            l[mt][0] += __low2float(hs0) + __high2float(hs0);
            l[mt][1] += __low2float(hs1) + __high2float(hs1);
        }

        // O += P V   (P aliases S)
        #pragma unroll
        for (int kt = 0; kt < 4; kt++) {
            #pragma unroll
            for (int ntp = 0; ntp < 4; ntp++) {
                uint32_t b[4];
                ldsm4(b, &Vb[(ntp * 16 + (mi >> 1) * 8 + r8) * KP + kt * 16 + (mi & 1) * 8]);
                #pragma unroll
                for (int mt = 0; mt < 2; mt++) {
                    uint32_t ap[4] = { s[mt][2 * kt][0], s[mt][2 * kt][1],
                                       s[mt][2 * kt + 1][0], s[mt][2 * kt + 1][1] };
                    mma16816(o_[mt][2 * ntp],     ap, b[0], b[1]);
                    mma16816(o_[mt][2 * ntp + 1], ap, b[2], b[3]);
                }
            }
        }
        __syncthreads();
    }

    // partial epilogue: quad row sums for l, write l (f32) + un-normalized O (f16)
    #pragma unroll
    for (int mt = 0; mt < 2; mt++)
        #pragma unroll
        for (int hh = 0; hh < 2; hh++) {
            l[mt][hh] += __shfl_xor_sync(0xffffffffu, l[mt][hh], 1);
            l[mt][hh] += __shfl_xor_sync(0xffffffffu, l[mt][hh], 2);
        }
    float* pl = g_pl + (size_t)split * NB * NH * HWD + (size_t)(n * NH + h) * HWD + q0;
    if (t4 == 0) {
        #pragma unroll
        for (int mt = 0; mt < 2; mt++) {
            int qr = w * 32 + mt * 16 + g;
            pl[qr]     = l[mt][0];
            pl[qr + 8] = l[mt][1];
        }
    }

    __syncthreads();
    #pragma unroll
    for (int mt = 0; mt < 2; mt++) {
        int qr = w * 32 + mt * 16 + g;
        #pragma unroll
        for (int nt = 0; nt < 8; nt++) {
            int d0 = nt * 8 + 2 * t4;
            *(uint32_t*)&SMh[qr * KP + d0]       = pack2(o_[mt][nt][0], o_[mt][nt][1]);
            *(uint32_t*)&SMh[(qr + 8) * KP + d0] = pack2(o_[mt][nt][2], o_[mt][nt][3]);
        }
    }
    __syncthreads();
    __half* po = g_po16 + (size_t)split * SPLIT_OFF + base;
    #pragma unroll
    for (int i = 0; i < 32; i++) {
        int f = tid + 128 * i;
        int qp = f & 63, d = f >> 6;
        __half2 hv = __halves2half2(SMh[(2 * qp) * KP + d], SMh[(2 * qp + 1) * KP + d]);
        *(uint32_t*)&po[(size_t)d * HWD + q0 + 2 * qp] = *(uint32_t*)&hv;
    }
}

// ---------------- split-K reduce: linv once per (head,q-tile), then stream ----------------
__global__ __launch_bounds__(256) void attn_reduce_kernel() {
    const int jt = blockIdx.x, nh = blockIdx.y;     // 32 j-tiles x 16 heads
    const int n = nh >> 2, h = nh & 3;
    const int j0 = jt * 128;
    __shared__ float linv[128];
    const int tid = threadIdx.x;
    if (tid < 128) {
        size_t off = (size_t)nh * HWD + j0 + tid;
        linv[tid] = 1.0f / (g_pl[off] + g_pl[(size_t)NB * NH * HWD + off]);
    }
    __syncthreads();
    const size_t base = ((size_t)n * CC + h * HD) * HWD;
    #pragma unroll
    for (int i = 0; i < 8; i++) {
        int f = tid + 256 * i;             // 2048 uint2 (4 halves each): 64 d x 128 j
        int d = f >> 5, qq = (f & 31) * 4;
        size_t off = base + (size_t)d * HWD + j0 + qq;
        uint2 a = *(const uint2*)&g_po16[off];
        uint2 b = *(const uint2*)&g_po16[SPLIT_OFF + off];
        __half2 a0 = u2h(a.x), a1 = u2h(a.y), b0 = u2h(b.x), b1 = u2h(b.y);
        float r0 = (__low2float(a0)  + __low2float(b0))  * linv[qq];
        float r1 = (__high2float(a0) + __high2float(b0)) * linv[qq + 1];
        float r2 = (__low2float(a1)  + __low2float(b1))  * linv[qq + 2];
        float r3 = (__high2float(a1) + __high2float(b1)) * linv[qq + 3];
        uint2 o;
        o.x = pack2(r0, r1);
        o.y = pack2(r2, r3);
        *(uint2*)&g_ao16[off] = o;
    }
}

// ---------------------------------------------------------------------------
extern "C" void kernel_launch(void* const* d_in, const int* in_sizes, int n_in,
                              void* d_out, int out_size) {
    const float* x      = (const float*)d_in[0];
    const float* mask   = (const float*)d_in[1];
    const float* norm_w = (const float*)d_in[2];
    const float* norm_b = (const float*)d_in[3];
    const float* qkv_w  = (const float*)d_in[4];
    const float* qkv_b  = (const float*)d_in[5];
    const float* proj_w = (const float*)d_in[6];
    const float* proj_b = (const float*)d_in[7];
    float* out = (float*)d_out;

    cudaFuncSetAttribute(gemm_qkv16_kernel,  cudaFuncAttributeMaxDynamicSharedMemorySize, QKV_SMEM);
    cudaFuncSetAttribute(gemm_proj16_kernel, cudaFuncAttributeMaxDynamicSharedMemorySize, PROJ_SMEM);

    gn_conv_kernel<<<256 + 1024, 256>>>(x, qkv_w, proj_w);
    gemm_qkv16_kernel<<<dim3(HWD / 128, (3 * CC) / 128, NB), 256, QKV_SMEM>>>(x, norm_w, norm_b, qkv_b);
    attn_kernel<<<dim3(HWD / 128, NB * NH, NSPLIT), 128>>>();
    attn_reduce_kernel<<<dim3(HWD / 128, NB * NH), 256>>>();
    int ny = (out_size >= NB * CC * HWD + NB * HWD) ? 3 : 2;
    gemm_proj16_kernel<<<dim3(HWD / 128, ny, NB), 256, PROJ_SMEM>>>(x, mask, proj_b, out);
}

// round 15
// speedup vs baseline: 1.0358x; 1.0018x over previous
#include <cuda_runtime.h>
#include <cuda_fp16.h>
#include <math.h>
#include <stdint.h>

#define NB 4
#define CC 256
#define HWD 4096
#define NH 4
#define HD 64
#define NGRP 8
#define GC 32
#define EPSV 1e-5f
#define LOG2E 1.44269504088896340736f
#define NSPLIT 2
#define SPLIT_OFF (NB * CC * HWD)
#define CHUNKS_PER_SPLIT (64 / NSPLIT)

// ---- scratch (allocation-free) ----
__device__ __half g_q16[NB * CC * HWD];
__device__ __half g_k16[NB * CC * HWD];
__device__ __half g_v16[NB * CC * HWD];
__device__ __half g_ao16[NB * CC * HWD];
__device__ __half g_qw16[3 * CC * CC];
__device__ __half g_pw16[CC * CC];
__device__ float  g_part[256 * 2];
__device__ __half g_po16[NSPLIT * NB * CC * HWD];   // partial O (f16, un-normalized)
__device__ float  g_pl[NSPLIT * NB * NH * HWD];     // partial l (f32)

// ---------------- helpers ----------------
__device__ __forceinline__ uint32_t h2ex2(uint32_t x) {
    uint32_t y; asm("ex2.approx.f16x2 %0, %1;" : "=r"(y) : "r"(x)); return y;
}
__device__ __forceinline__ uint32_t pack2(float a, float b) {
    __half2 h = __floats2half2_rn(a, b);
    return *reinterpret_cast<uint32_t*>(&h);
}
__device__ __forceinline__ __half2 u2h(uint32_t u) { return *reinterpret_cast<__half2*>(&u); }
__device__ __forceinline__ uint32_t sptr(const void* p) {
    return (uint32_t)__cvta_generic_to_shared(p);
}
__device__ __forceinline__ void cp16(void* dst, const void* src) {
    asm volatile("cp.async.cg.shared.global [%0], [%1], 16;\n"
                 :: "r"(sptr(dst)), "l"(src));
}
__device__ __forceinline__ void ldsm4t(uint32_t* f, const void* p) {
    asm volatile("ldmatrix.sync.aligned.m8n8.x4.trans.shared.b16 {%0,%1,%2,%3}, [%4];\n"
                 : "=r"(f[0]), "=r"(f[1]), "=r"(f[2]), "=r"(f[3]) : "r"(sptr(p)));
}
__device__ __forceinline__ void ldsm4(uint32_t* f, const void* p) {
    asm volatile("ldmatrix.sync.aligned.m8n8.x4.shared.b16 {%0,%1,%2,%3}, [%4];\n"
                 : "=r"(f[0]), "=r"(f[1]), "=r"(f[2]), "=r"(f[3]) : "r"(sptr(p)));
}
__device__ __forceinline__ void mma16816(float* c, const uint32_t* a, uint32_t b0, uint32_t b1) {
    asm volatile(
        "mma.sync.aligned.m16n8k16.row.col.f32.f16.f16.f32 "
        "{%0,%1,%2,%3}, {%4,%5,%6,%7}, {%8,%9}, {%0,%1,%2,%3};\n"
        : "+f"(c[0]), "+f"(c[1]), "+f"(c[2]), "+f"(c[3])
        : "r"(a[0]), "r"(a[1]), "r"(a[2]), "r"(a[3]), "r"(b0), "r"(b1));
}
__device__ __forceinline__ void mma16816h(uint32_t* c, const uint32_t* a, uint32_t b0, uint32_t b1) {
    asm volatile(
        "mma.sync.aligned.m16n8k16.row.col.f16.f16.f16.f16 "
        "{%0,%1}, {%2,%3,%4,%5}, {%6,%7}, {%0,%1};\n"
        : "+r"(c[0]), "+r"(c[1])
        : "r"(a[0]), "r"(a[1]), "r"(a[2]), "r"(a[3]), "r"(b0), "r"(b1));
}

// ---------------- GroupNorm partials + weight conversion (fused launch) ----------------
__global__ void gn_conv_kernel(const float* __restrict__ x,
                               const float* __restrict__ qw, const float* __restrict__ pw) {
    if (blockIdx.x >= 256) {
        int i = (blockIdx.x - 256) * 256 + threadIdx.x;
        if (i < 3 * CC * CC) g_qw16[i] = __float2half(qw[i]);
        if (i < CC * CC)     g_pw16[i] = __float2half(pw[i]);
        return;
    }
    int ng = blockIdx.x >> 3, part = blockIdx.x & 7;
    const float4* xp = (const float4*)(x + (size_t)ng * GC * HWD);
    float s = 0.f, ss = 0.f;
    int i0 = part * 4096;
    for (int i = i0 + threadIdx.x; i < i0 + 4096; i += 256) {
        float4 v = xp[i];
        s  += v.x + v.y + v.z + v.w;
        ss += v.x * v.x + v.y * v.y + v.z * v.z + v.w * v.w;
    }
    #pragma unroll
    for (int off = 16; off; off >>= 1) {
        s  += __shfl_down_sync(0xffffffffu, s, off);
        ss += __shfl_down_sync(0xffffffffu, ss, off);
    }
    __shared__ float sh[16];
    int w = threadIdx.x >> 5;
    if ((threadIdx.x & 31) == 0) { sh[w] = s; sh[8 + w] = ss; }
    __syncthreads();
    if (threadIdx.x == 0) {
        float S = 0.f, SS = 0.f;
        #pragma unroll
        for (int i = 0; i < 8; i++) { S += sh[i]; SS += sh[8 + i]; }
        g_part[blockIdx.x * 2] = S; g_part[blockIdx.x * 2 + 1] = SS;
    }
}

// ---------------- fused GN + QKV GEMM (fp16 tensor core) ----------------
#define GA_ST 5120
#define GB_OFF (3 * GA_ST)
#define GB_ST 4352
#define QKV_SMEM ((GB_OFF + 2 * GB_ST) * 2)

__global__ __launch_bounds__(256, 2) void gemm_qkv16_kernel(
    const float* __restrict__ x,
    const float* __restrict__ nw, const float* __restrict__ nb_,
    const float* __restrict__ qkv_b)
{
    extern __shared__ __align__(16) __half GS[];
    __shared__ float sc[CC], bc[CC];
    const int n  = blockIdx.z;
    const int o0 = blockIdx.y * 128;
    const int j0 = blockIdx.x * 128;

    const int tid = threadIdx.x, w = tid >> 5, lane = tid & 31;
    const int wm = w >> 1, wn = w & 1;
    const int g = lane >> 2, t4 = lane & 3, mi = lane >> 3, r8 = lane & 7;
    const int la = lane & 15, ha = lane >> 4;

    {
        int c = tid;
        int ng = n * NGRP + c / GC;
        float s = 0.f, ss = 0.f;
        #pragma unroll
        for (int p = 0; p < 8; p++) {
            s  += g_part[(ng * 8 + p) * 2];
            ss += g_part[(ng * 8 + p) * 2 + 1];
        }
        const float invn = 1.0f / (float)(GC * HWD);
        float m  = s * invn;
        float rs = rsqrtf(ss * invn - m * m + EPSV);
        float scv = rs * nw[c];
        sc[c] = scv;
        bc[c] = nb_[c] - m * scv;
    }

    auto prefetchA = [&](int buf, int k0) {
        __half* Ab = GS + buf * GA_ST;
        #pragma unroll
        for (int i = 0; i < 2; i++) {
            int s = tid + 256 * i;
            int row = s >> 2, c8 = (s & 3) * 8;
            cp16(&Ab[row * 40 + c8], &g_qw16[(size_t)(o0 + row) * CC + k0 + c8]);
        }
        asm volatile("cp.async.commit_group;\n");
    };

    const float* xb = x + (size_t)n * CC * HWD;
    const int brow = tid >> 3;
    const int bj   = (tid & 7) * 16;
    uint32_t breg[8];
    auto loadB = [&](int k0) {
        float scv = sc[k0 + brow], bcv = bc[k0 + brow];
        const float* src = xb + (size_t)(k0 + brow) * HWD + j0 + bj;
        #pragma unroll
        for (int i = 0; i < 4; i++) {
            float4 v = *(const float4*)(src + 4 * i);
            breg[2 * i]     = pack2(v.x * scv + bcv, v.y * scv + bcv);
            breg[2 * i + 1] = pack2(v.z * scv + bcv, v.w * scv + bcv);
        }
    };
    auto stsB = [&](int buf) {
        __half* Bb = GS + GB_OFF + buf * GB_ST;
        *(uint4*)&Bb[brow * 136 + bj]     = *(uint4*)&breg[0];
        *(uint4*)&Bb[brow * 136 + bj + 8] = *(uint4*)&breg[4];
    };

    prefetchA(0, 0);
    prefetchA(1, 32);
    __syncthreads();
    loadB(0);

    float acc[2][8][4] = {};
    for (int c = 0; c < 8; c++) {
        stsB(c & 1);
        if (c < 7)  asm volatile("cp.async.wait_group 1;\n");
        else        asm volatile("cp.async.wait_group 0;\n");
        __syncthreads();
        if (c + 2 < 8) prefetchA((c + 2) % 3, (c + 2) * 32);
        if (c + 1 < 8) loadB((c + 1) * 32);

        __half* Ab = GS + (c % 3) * GA_ST;
        __half* Bb = GS + GB_OFF + (c & 1) * GB_ST;
        #pragma unroll
        for (int ks = 0; ks < 2; ks++) {
            uint32_t a[2][4];
            #pragma unroll
            for (int mt = 0; mt < 2; mt++)
                ldsm4(a[mt], &Ab[(wm * 32 + mt * 16 + la) * 40 + ks * 16 + ha * 8]);
            #pragma unroll
            for (int nb = 0; nb < 4; nb++) {
                uint32_t b[4];
                ldsm4t(b, &Bb[(ks * 16 + (mi & 1) * 8 + r8) * 136 + wn * 64 + nb * 16 + (mi >> 1) * 8]);
                #pragma unroll
                for (int mt = 0; mt < 2; mt++) {
                    mma16816(acc[mt][2 * nb],     a[mt], b[0], b[1]);
                    mma16816(acc[mt][2 * nb + 1], a[mt], b[2], b[3]);
                }
            }
        }
        __syncthreads();
    }

    const int part = o0 >> 8;
    __half* dst = (part == 0) ? g_q16 : ((part == 1) ? g_k16 : g_v16);
    const float scale = (part == 0) ? (0.125f * LOG2E) : 1.0f;
    #pragma unroll
    for (int mt = 0; mt < 2; mt++) {
        int o_lo = o0 + wm * 32 + mt * 16 + g;
        float b_lo = qkv_b[o_lo], b_hi = qkv_b[o_lo + 8];
        int c_lo = o_lo & 255;
        #pragma unroll
        for (int nt = 0; nt < 8; nt++) {
            int j = j0 + wn * 64 + nt * 8 + 2 * t4;
            *(uint32_t*)&dst[((size_t)n * CC + c_lo) * HWD + j] =
                pack2((acc[mt][nt][0] + b_lo) * scale, (acc[mt][nt][1] + b_lo) * scale);
            *(uint32_t*)&dst[((size_t)n * CC + c_lo + 8) * HWD + j] =
                pack2((acc[mt][nt][2] + b_hi) * scale, (acc[mt][nt][3] + b_hi) * scale);
        }
    }
}

// ---------------- proj GEMM + residual + mask (cp.async B from ao16) ----------------
#define PROJ_SMEM ((GB_OFF + 3 * GB_ST) * 2)

__global__ __launch_bounds__(256, 2) void gemm_proj16_kernel(
    const float* __restrict__ x, const float* __restrict__ mask,
    const float* __restrict__ pb, float* __restrict__ out)
{
    extern __shared__ __align__(16) __half GS[];
    const int n  = blockIdx.z;
    const int j0 = blockIdx.x * 128;

    if (blockIdx.y == 2) {   // mask copy tail (full-width: 2 elems/thread over 128 j? just j0..j0+127)
        int t = threadIdx.x;
        if (t < 128) {
            float* mout = out + (size_t)NB * CC * HWD;
            int idx = n * HWD + j0 + t;
            mout[idx] = mask[idx];
        }
        return;
    }
    const int o0 = blockIdx.y * 128;

    const int tid = threadIdx.x, w = tid >> 5, lane = tid & 31;
    const int wm = w >> 1, wn = w & 1;
    const int g = lane >> 2, t4 = lane & 3, mi = lane >> 3, r8 = lane & 7;
    const int la = lane & 15, ha = lane >> 4;
    const __half* Bsrc = g_ao16 + (size_t)n * CC * HWD;

    auto prefetch = [&](int buf, int k0) {
        __half* Ab = GS + buf * GA_ST;
        __half* Bb = GS + GB_OFF + buf * GB_ST;
        #pragma unroll
        for (int i = 0; i < 2; i++) {
            int s = tid + 256 * i;
            int row = s >> 2, c8 = (s & 3) * 8;
            cp16(&Ab[row * 40 + c8], &g_pw16[(size_t)(o0 + row) * CC + k0 + c8]);
        }
        #pragma unroll
        for (int i = 0; i < 2; i++) {
            int s = tid + 256 * i;
            int row = s >> 4, c8 = (s & 15) * 8;
            cp16(&Bb[row * 136 + c8], &Bsrc[(size_t)(k0 + row) * HWD + j0 + c8]);
        }
        asm volatile("cp.async.commit_group;\n");
    };

    float acc[2][8][4] = {};
    prefetch(0, 0);
    prefetch(1, 32);
    for (int c = 0; c < 8; c++) {
        if (c < 7) asm volatile("cp.async.wait_group 1;\n");
        else       asm volatile("cp.async.wait_group 0;\n");
        __syncthreads();
        if (c + 2 < 8) prefetch((c + 2) % 3, (c + 2) * 32);
        int buf = c % 3;
        __half* Ab = GS + buf * GA_ST;
        __half* Bb = GS + GB_OFF + buf * GB_ST;
        #pragma unroll
        for (int ks = 0; ks < 2; ks++) {
            uint32_t a[2][4];
            #pragma unroll
            for (int mt = 0; mt < 2; mt++)
                ldsm4(a[mt], &Ab[(wm * 32 + mt * 16 + la) * 40 + ks * 16 + ha * 8]);
            #pragma unroll
            for (int nb = 0; nb < 4; nb++) {
                uint32_t b[4];
                ldsm4t(b, &Bb[(ks * 16 + (mi & 1) * 8 + r8) * 136 + wn * 64 + nb * 16 + (mi >> 1) * 8]);
                #pragma unroll
                for (int mt = 0; mt < 2; mt++) {
                    mma16816(acc[mt][2 * nb],     a[mt], b[0], b[1]);
                    mma16816(acc[mt][2 * nb + 1], a[mt], b[2], b[3]);
                }
            }
        }
    }

    #pragma unroll
    for (int mt = 0; mt < 2; mt++) {
        int o_lo = o0 + wm * 32 + mt * 16 + g;
        float b_lo = pb[o_lo], b_hi = pb[o_lo + 8];
        #pragma unroll
        for (int nt = 0; nt < 8; nt++) {
            int j = j0 + wn * 64 + nt * 8 + 2 * t4;
            float2 mv = *(const float2*)&mask[(size_t)n * HWD + j];
            size_t off = ((size_t)n * CC + o_lo) * HWD + j;
            float2 xv = *(const float2*)&x[off];
            float2 r;
            r.x = (xv.x + acc[mt][nt][0] + b_lo) * mv.x;
            r.y = (xv.y + acc[mt][nt][1] + b_lo) * mv.y;
            *(float2*)&out[off] = r;
            size_t off2 = off + 8 * HWD;
            float2 xv2 = *(const float2*)&x[off2];
            float2 r2;
            r2.x = (xv2.x + acc[mt][nt][2] + b_hi) * mv.x;
            r2.y = (xv2.y + acc[mt][nt][3] + b_hi) * mv.y;
            *(float2*)&out[off2] = r2;
        }
    }
}

// ---------------- Flash attention: split-K x2, fixed-bias softmax, f16 partials ----------------
#define KP 72
#define QP 136
#define BIAS_H2 0xC800C800u   // f16x2 {-8, -8}
__global__ __launch_bounds__(128, 3) void attn_kernel() {
    __shared__ __align__(16) __half SMh[18432];   // 36864 B
    const int n = blockIdx.y >> 2, h = blockIdx.y & 3;
    const int q0 = blockIdx.x * 128;
    const int split = blockIdx.z;
    const int c0 = split * CHUNKS_PER_SPLIT;
    const size_t base = (size_t)(n * CC + h * HD) * HWD;
    const __half* qg = g_q16 + base;
    const __half* kg = g_k16 + base;
    const __half* vg = g_v16 + base;

    const int tid = threadIdx.x, w = tid >> 5, lane = tid & 31;
    const int g = lane >> 2, t4 = lane & 3, mi = lane >> 3, r8 = lane & 7;

    #pragma unroll
    for (int i = 0; i < 8; i++) {
        int s = tid + 128 * i;
        int row = s >> 4, c8 = (s & 15) * 8;
        *(uint4*)&SMh[row * QP + c8] = *(const uint4*)&qg[(size_t)row * HWD + q0 + c8];
    }
    __syncthreads();
    uint32_t aq[2][4][4];
    #pragma unroll
    for (int mt = 0; mt < 2; mt++)
        #pragma unroll
        for (int kt = 0; kt < 4; kt++)
            ldsm4t(aq[mt][kt],
                   &SMh[(kt * 16 + (mi >> 1) * 8 + r8) * QP + w * 32 + mt * 16 + (mi & 1) * 8]);
    __syncthreads();

    auto prefetch = [&](int buf, int c) {
        int jc = c * 64;
        __half* Kb = &SMh[buf * 4608];
        __half* Vb = &SMh[9216 + buf * 4608];
        #pragma unroll
        for (int i = 0; i < 4; i++) {
            int s = tid + 128 * i;
            int row = s >> 3, c8 = (s & 7) * 8;
            cp16(&Kb[row * KP + c8], &kg[(size_t)row * HWD + jc + c8]);
            cp16(&Vb[row * KP + c8], &vg[(size_t)row * HWD + jc + c8]);
        }
        asm volatile("cp.async.commit_group;\n");
    };

    float o_[2][8][4] = {};
    float l[2][2] = {};

    prefetch(0, c0);
    for (int c = c0; c < c0 + CHUNKS_PER_SPLIT; c++) {
        int buf = c & 1;
        if (c + 1 < c0 + CHUNKS_PER_SPLIT) { prefetch(buf ^ 1, c + 1); asm volatile("cp.async.wait_group 1;\n"); }
        else                               { asm volatile("cp.async.wait_group 0;\n"); }
        __syncthreads();
        const __half* Kb = &SMh[buf * 4608];
        const __half* Vb = &SMh[9216 + buf * 4608];

        // S = Q K^T + (-8), f16 accumulators
        uint32_t s[2][8][2];
        #pragma unroll
        for (int mt = 0; mt < 2; mt++)
            #pragma unroll
            for (int nt = 0; nt < 8; nt++) { s[mt][nt][0] = BIAS_H2; s[mt][nt][1] = BIAS_H2; }
        #pragma unroll
        for (int kt = 0; kt < 4; kt++) {
            #pragma unroll
            for (int ntp = 0; ntp < 4; ntp++) {
                uint32_t b[4];
                ldsm4t(b, &Kb[(kt * 16 + (mi & 1) * 8 + r8) * KP + ntp * 16 + (mi >> 1) * 8]);
                #pragma unroll
                for (int mt = 0; mt < 2; mt++) {
                    mma16816h(s[mt][2 * ntp],     aq[mt][kt], b[0], b[1]);
                    mma16816h(s[mt][2 * ntp + 1], aq[mt][kt], b[2], b[3]);
                }
            }
        }

        // p = exp2(s - 8) in place; accumulate row sums
        #pragma unroll
        for (int mt = 0; mt < 2; mt++) {
            __half2 hs0 = __floats2half2_rn(0.f, 0.f), hs1 = hs0;
            #pragma unroll
            for (int nt = 0; nt < 8; nt++) {
                uint32_t p0 = h2ex2(s[mt][nt][0]);
                uint32_t p1 = h2ex2(s[mt][nt][1]);
                s[mt][nt][0] = p0; s[mt][nt][1] = p1;
                hs0 = __hadd2(hs0, u2h(p0));
                hs1 = __hadd2(hs1, u2h(p1));
            }
            l[mt][0] += __low2float(hs0) + __high2float(hs0);
            l[mt][1] += __low2float(hs1) + __high2float(hs1);
        }

        // O += P V   (P aliases S)
        #pragma unroll
        for (int kt = 0; kt < 4; kt++) {
            #pragma unroll
            for (int ntp = 0; ntp < 4; ntp++) {
                uint32_t b[4];
                ldsm4(b, &Vb[(ntp * 16 + (mi >> 1) * 8 + r8) * KP + kt * 16 + (mi & 1) * 8]);
                #pragma unroll
                for (int mt = 0; mt < 2; mt++) {
                    uint32_t ap[4] = { s[mt][2 * kt][0], s[mt][2 * kt][1],
                                       s[mt][2 * kt + 1][0], s[mt][2 * kt + 1][1] };
                    mma16816(o_[mt][2 * ntp],     ap, b[0], b[1]);
                    mma16816(o_[mt][2 * ntp + 1], ap, b[2], b[3]);
                }
            }
        }
        __syncthreads();
    }

    // partial epilogue: quad row sums for l, write l (f32) + un-normalized O (f16)
    #pragma unroll
    for (int mt = 0; mt < 2; mt++)
        #pragma unroll
        for (int hh = 0; hh < 2; hh++) {
            l[mt][hh] += __shfl_xor_sync(0xffffffffu, l[mt][hh], 1);
            l[mt][hh] += __shfl_xor_sync(0xffffffffu, l[mt][hh], 2);
        }
    float* pl = g_pl + (size_t)split * NB * NH * HWD + (size_t)(n * NH + h) * HWD + q0;
    if (t4 == 0) {
        #pragma unroll
        for (int mt = 0; mt < 2; mt++) {
            int qr = w * 32 + mt * 16 + g;
            pl[qr]     = l[mt][0];
            pl[qr + 8] = l[mt][1];
        }
    }

    __syncthreads();
    #pragma unroll
    for (int mt = 0; mt < 2; mt++) {
        int qr = w * 32 + mt * 16 + g;
        #pragma unroll
        for (int nt = 0; nt < 8; nt++) {
            int d0 = nt * 8 + 2 * t4;
            *(uint32_t*)&SMh[qr * KP + d0]       = pack2(o_[mt][nt][0], o_[mt][nt][1]);
            *(uint32_t*)&SMh[(qr + 8) * KP + d0] = pack2(o_[mt][nt][2], o_[mt][nt][3]);
        }
    }
    __syncthreads();
    __half* po = g_po16 + (size_t)split * SPLIT_OFF + base;
    #pragma unroll
    for (int i = 0; i < 32; i++) {
        int f = tid + 128 * i;
        int qp = f & 63, d = f >> 6;
        __half2 hv = __halves2half2(SMh[(2 * qp) * KP + d], SMh[(2 * qp + 1) * KP + d]);
        *(uint32_t*)&po[(size_t)d * HWD + q0 + 2 * qp] = *(uint32_t*)&hv;
    }
}

// ---------------- split-K reduce: high-parallelism streaming combine ----------------
// grid: (32 j-tiles, 16 heads, 4 d-slices); each block: 16 d x 128 j, 2 iters/thread.
__global__ __launch_bounds__(256) void attn_reduce_kernel() {
    const int jt = blockIdx.x, nh = blockIdx.y, ds = blockIdx.z;
    const int n = nh >> 2, h = nh & 3;
    const int j0 = jt * 128;
    const int d0 = ds * 16;
    __shared__ float linv[128];
    const int tid = threadIdx.x;
    if (tid < 128) {
        size_t off = (size_t)nh * HWD + j0 + tid;
        linv[tid] = 1.0f / (g_pl[off] + g_pl[(size_t)NB * NH * HWD + off]);
    }
    __syncthreads();
    const size_t base = ((size_t)n * CC + h * HD + d0) * HWD;
    #pragma unroll
    for (int i = 0; i < 2; i++) {
        int f = tid + 256 * i;             // 512 uint2 (4 halves each): 16 d x 128 j
        int d = f >> 5, qq = (f & 31) * 4;
        size_t off = base + (size_t)d * HWD + j0 + qq;
        uint2 a = *(const uint2*)&g_po16[off];
        uint2 b = *(const uint2*)&g_po16[SPLIT_OFF + off];
        __half2 a0 = u2h(a.x), a1 = u2h(a.y), b0 = u2h(b.x), b1 = u2h(b.y);
        float r0 = (__low2float(a0)  + __low2float(b0))  * linv[qq];
        float r1 = (__high2float(a0) + __high2float(b0)) * linv[qq + 1];
        float r2 = (__low2float(a1)  + __low2float(b1))  * linv[qq + 2];
        float r3 = (__high2float(a1) + __high2float(b1)) * linv[qq + 3];
        uint2 o;
        o.x = pack2(r0, r1);
        o.y = pack2(r2, r3);
        *(uint2*)&g_ao16[off] = o;
    }
}

// ---------------------------------------------------------------------------
extern "C" void kernel_launch(void* const* d_in, const int* in_sizes, int n_in,
                              void* d_out, int out_size) {
    const float* x      = (const float*)d_in[0];
    const float* mask   = (const float*)d_in[1];
    const float* norm_w = (const float*)d_in[2];
    const float* norm_b = (const float*)d_in[3];
    const float* qkv_w  = (const float*)d_in[4];
    const float* qkv_b  = (const float*)d_in[5];
    const float* proj_w = (const float*)d_in[6];
    const float* proj_b = (const float*)d_in[7];
    float* out = (float*)d_out;

    cudaFuncSetAttribute(gemm_qkv16_kernel,  cudaFuncAttributeMaxDynamicSharedMemorySize, QKV_SMEM);
    cudaFuncSetAttribute(gemm_proj16_kernel, cudaFuncAttributeMaxDynamicSharedMemorySize, PROJ_SMEM);

    gn_conv_kernel<<<256 + 1024, 256>>>(x, qkv_w, proj_w);
    gemm_qkv16_kernel<<<dim3(HWD / 128, (3 * CC) / 128, NB), 256, QKV_SMEM>>>(x, norm_w, norm_b, qkv_b);
    attn_kernel<<<dim3(HWD / 128, NB * NH, NSPLIT), 128>>>();
    attn_reduce_kernel<<<dim3(HWD / 128, NB * NH, 4), 256>>>();
    int ny = (out_size >= NB * CC * HWD + NB * HWD) ? 3 : 2;
    gemm_proj16_kernel<<<dim3(HWD / 128, ny, NB), 256, PROJ_SMEM>>>(x, mask, proj_b, out);
}

// round 16
// speedup vs baseline: 1.0361x; 1.0003x over previous
#include <cuda_runtime.h>
#include <cuda_fp16.h>
#include <math.h>
#include <stdint.h>

#define NB 4
#define CC 256
#define HWD 4096
#define NH 4
#define HD 64
#define NGRP 8
#define GC 32
#define EPSV 1e-5f
#define LOG2E 1.44269504088896340736f
#define NSPLIT 2
#define SPLIT_OFF (NB * CC * HWD)
#define CHUNKS_PER_SPLIT (64 / NSPLIT)
#define GNP 32    // gn partials per group

// ---- scratch (allocation-free) ----
__device__ __half g_q16[NB * CC * HWD];
__device__ __half g_k16[NB * CC * HWD];
__device__ __half g_v16[NB * CC * HWD];
__device__ __half g_ao16[NB * CC * HWD];
__device__ __half g_qw16[3 * CC * CC];
__device__ __half g_pw16[CC * CC];
__device__ float  g_part[NB * NGRP * GNP * 2];
__device__ __half g_po16[NSPLIT * NB * CC * HWD];   // partial O (f16, un-normalized)
__device__ float  g_pl[NSPLIT * NB * NH * HWD];     // partial l (f32)

// ---------------- helpers ----------------
__device__ __forceinline__ uint32_t h2ex2(uint32_t x) {
    uint32_t y; asm("ex2.approx.f16x2 %0, %1;" : "=r"(y) : "r"(x)); return y;
}
__device__ __forceinline__ uint32_t pack2(float a, float b) {
    __half2 h = __floats2half2_rn(a, b);
    return *reinterpret_cast<uint32_t*>(&h);
}
__device__ __forceinline__ __half2 u2h(uint32_t u) { return *reinterpret_cast<__half2*>(&u); }
__device__ __forceinline__ uint32_t sptr(const void* p) {
    return (uint32_t)__cvta_generic_to_shared(p);
}
__device__ __forceinline__ void cp16(void* dst, const void* src) {
    asm volatile("cp.async.cg.shared.global [%0], [%1], 16;\n"
                 :: "r"(sptr(dst)), "l"(src));
}
__device__ __forceinline__ void ldsm4t(uint32_t* f, const void* p) {
    asm volatile("ldmatrix.sync.aligned.m8n8.x4.trans.shared.b16 {%0,%1,%2,%3}, [%4];\n"
                 : "=r"(f[0]), "=r"(f[1]), "=r"(f[2]), "=r"(f[3]) : "r"(sptr(p)));
}
__device__ __forceinline__ void ldsm4(uint32_t* f, const void* p) {
    asm volatile("ldmatrix.sync.aligned.m8n8.x4.shared.b16 {%0,%1,%2,%3}, [%4];\n"
                 : "=r"(f[0]), "=r"(f[1]), "=r"(f[2]), "=r"(f[3]) : "r"(sptr(p)));
}
__device__ __forceinline__ void mma16816(float* c, const uint32_t* a, uint32_t b0, uint32_t b1) {
    asm volatile(
        "mma.sync.aligned.m16n8k16.row.col.f32.f16.f16.f32 "
        "{%0,%1,%2,%3}, {%4,%5,%6,%7}, {%8,%9}, {%0,%1,%2,%3};\n"
        : "+f"(c[0]), "+f"(c[1]), "+f"(c[2]), "+f"(c[3])
        : "r"(a[0]), "r"(a[1]), "r"(a[2]), "r"(a[3]), "r"(b0), "r"(b1));
}
__device__ __forceinline__ void mma16816h(uint32_t* c, const uint32_t* a, uint32_t b0, uint32_t b1) {
    asm volatile(
        "mma.sync.aligned.m16n8k16.row.col.f16.f16.f16.f16 "
        "{%0,%1}, {%2,%3,%4,%5}, {%6,%7}, {%0,%1};\n"
        : "+r"(c[0]), "+r"(c[1])
        : "r"(a[0]), "r"(a[1]), "r"(a[2]), "r"(a[3]), "r"(b0), "r"(b1));
}

// ---------------- GroupNorm partials (32/group) + weight conversion ----------------
__global__ void gn_conv_kernel(const float* __restrict__ x,
                               const float* __restrict__ qw, const float* __restrict__ pw) {
    if (blockIdx.x >= NB * NGRP * GNP) {
        int i = (blockIdx.x - NB * NGRP * GNP) * 256 + threadIdx.x;
        if (i < 3 * CC * CC) g_qw16[i] = __float2half(qw[i]);
        if (i < CC * CC)     g_pw16[i] = __float2half(pw[i]);
        return;
    }
    int ng = blockIdx.x >> 5, part = blockIdx.x & 31;
    const float4* xp = (const float4*)(x + (size_t)ng * GC * HWD);
    float s = 0.f, ss = 0.f;
    int i0 = part * 1024;
    #pragma unroll
    for (int k = 0; k < 4; k++) {
        float4 v = xp[i0 + threadIdx.x + 256 * k];
        s  += v.x + v.y + v.z + v.w;
        ss += v.x * v.x + v.y * v.y + v.z * v.z + v.w * v.w;
    }
    #pragma unroll
    for (int off = 16; off; off >>= 1) {
        s  += __shfl_down_sync(0xffffffffu, s, off);
        ss += __shfl_down_sync(0xffffffffu, ss, off);
    }
    __shared__ float sh[16];
    int w = threadIdx.x >> 5;
    if ((threadIdx.x & 31) == 0) { sh[w] = s; sh[8 + w] = ss; }
    __syncthreads();
    if (threadIdx.x == 0) {
        float S = 0.f, SS = 0.f;
        #pragma unroll
        for (int i = 0; i < 8; i++) { S += sh[i]; SS += sh[8 + i]; }
        g_part[blockIdx.x * 2] = S; g_part[blockIdx.x * 2 + 1] = SS;
    }
}

// ---------------- fused GN + QKV GEMM: 3-buffer B ring, 1 sync/chunk ----------------
#define GA_ST 5120
#define GB_OFF (3 * GA_ST)
#define GB_ST 4352
#define QKV_SMEM ((GB_OFF + 3 * GB_ST) * 2)

__global__ __launch_bounds__(256, 2) void gemm_qkv16_kernel(
    const float* __restrict__ x,
    const float* __restrict__ nw, const float* __restrict__ nb_,
    const float* __restrict__ qkv_b)
{
    extern __shared__ __align__(16) __half GS[];
    __shared__ float sc[CC], bc[CC];
    const int n  = blockIdx.z;
    const int o0 = blockIdx.y * 128;
    const int j0 = blockIdx.x * 128;

    const int tid = threadIdx.x, w = tid >> 5, lane = tid & 31;
    const int wm = w >> 1, wn = w & 1;
    const int g = lane >> 2, t4 = lane & 3, mi = lane >> 3, r8 = lane & 7;
    const int la = lane & 15, ha = lane >> 4;

    {
        int c = tid;
        int ng = n * NGRP + c / GC;
        float s = 0.f, ss = 0.f;
        #pragma unroll
        for (int p = 0; p < GNP; p++) {
            s  += g_part[(ng * GNP + p) * 2];
            ss += g_part[(ng * GNP + p) * 2 + 1];
        }
        const float invn = 1.0f / (float)(GC * HWD);
        float m  = s * invn;
        float rs = rsqrtf(ss * invn - m * m + EPSV);
        float scv = rs * nw[c];
        sc[c] = scv;
        bc[c] = nb_[c] - m * scv;
    }

    auto prefetchA = [&](int buf, int k0) {
        __half* Ab = GS + buf * GA_ST;
        #pragma unroll
        for (int i = 0; i < 2; i++) {
            int s = tid + 256 * i;
            int row = s >> 2, c8 = (s & 3) * 8;
            cp16(&Ab[row * 40 + c8], &g_qw16[(size_t)(o0 + row) * CC + k0 + c8]);
        }
        asm volatile("cp.async.commit_group;\n");
    };

    const float* xb = x + (size_t)n * CC * HWD;
    const int brow = tid >> 3;
    const int bj   = (tid & 7) * 16;
    uint32_t breg[8];
    auto loadB = [&](int k0) {
        float scv = sc[k0 + brow], bcv = bc[k0 + brow];
        const float* src = xb + (size_t)(k0 + brow) * HWD + j0 + bj;
        #pragma unroll
        for (int i = 0; i < 4; i++) {
            float4 v = *(const float4*)(src + 4 * i);
            breg[2 * i]     = pack2(v.x * scv + bcv, v.y * scv + bcv);
            breg[2 * i + 1] = pack2(v.z * scv + bcv, v.w * scv + bcv);
        }
    };
    auto stsB = [&](int buf) {
        __half* Bb = GS + GB_OFF + buf * GB_ST;
        *(uint4*)&Bb[brow * 136 + bj]     = *(uint4*)&breg[0];
        *(uint4*)&Bb[brow * 136 + bj + 8] = *(uint4*)&breg[4];
    };

    prefetchA(0, 0);
    prefetchA(1, 32);
    __syncthreads();        // sc/bc ready
    loadB(0);

    float acc[2][8][4] = {};
    for (int c = 0; c < 8; c++) {
        stsB(c % 3);
        if (c < 7)  asm volatile("cp.async.wait_group 1;\n");
        else        asm volatile("cp.async.wait_group 0;\n");
        __syncthreads();    // single barrier: orders stsB(c) writes before reads below
        if (c + 2 < 8) prefetchA((c + 2) % 3, (c + 2) * 32);
        if (c + 1 < 8) loadB((c + 1) * 32);

        __half* Ab = GS + (c % 3) * GA_ST;
        __half* Bb = GS + GB_OFF + (c % 3) * GB_ST;
        #pragma unroll
        for (int ks = 0; ks < 2; ks++) {
            uint32_t a[2][4];
            #pragma unroll
            for (int mt = 0; mt < 2; mt++)
                ldsm4(a[mt], &Ab[(wm * 32 + mt * 16 + la) * 40 + ks * 16 + ha * 8]);
            #pragma unroll
            for (int nb = 0; nb < 4; nb++) {
                uint32_t b[4];
                ldsm4t(b, &Bb[(ks * 16 + (mi & 1) * 8 + r8) * 136 + wn * 64 + nb * 16 + (mi >> 1) * 8]);
                #pragma unroll
                for (int mt = 0; mt < 2; mt++) {
                    mma16816(acc[mt][2 * nb],     a[mt], b[0], b[1]);
                    mma16816(acc[mt][2 * nb + 1], a[mt], b[2], b[3]);
                }
            }
        }
    }

    const int part = o0 >> 8;
    __half* dst = (part == 0) ? g_q16 : ((part == 1) ? g_k16 : g_v16);
    const float scale = (part == 0) ? (0.125f * LOG2E) : 1.0f;
    #pragma unroll
    for (int mt = 0; mt < 2; mt++) {
        int o_lo = o0 + wm * 32 + mt * 16 + g;
        float b_lo = qkv_b[o_lo], b_hi = qkv_b[o_lo + 8];
        int c_lo = o_lo & 255;
        #pragma unroll
        for (int nt = 0; nt < 8; nt++) {
            int j = j0 + wn * 64 + nt * 8 + 2 * t4;
            *(uint32_t*)&dst[((size_t)n * CC + c_lo) * HWD + j] =
                pack2((acc[mt][nt][0] + b_lo) * scale, (acc[mt][nt][1] + b_lo) * scale);
            *(uint32_t*)&dst[((size_t)n * CC + c_lo + 8) * HWD + j] =
                pack2((acc[mt][nt][2] + b_hi) * scale, (acc[mt][nt][3] + b_hi) * scale);
        }
    }
}

// ---------------- proj GEMM + residual + mask (cp.async B from ao16) ----------------
#define PROJ_SMEM ((GB_OFF + 3 * GB_ST) * 2)

__global__ __launch_bounds__(256, 2) void gemm_proj16_kernel(
    const float* __restrict__ x, const float* __restrict__ mask,
    const float* __restrict__ pb, float* __restrict__ out)
{
    extern __shared__ __align__(16) __half GS[];
    const int n  = blockIdx.z;
    const int j0 = blockIdx.x * 128;

    if (blockIdx.y == 2) {   // mask copy tail
        int t = threadIdx.x;
        if (t < 128) {
            float* mout = out + (size_t)NB * CC * HWD;
            int idx = n * HWD + j0 + t;
            mout[idx] = mask[idx];
        }
        return;
    }
    const int o0 = blockIdx.y * 128;

    const int tid = threadIdx.x, w = tid >> 5, lane = tid & 31;
    const int wm = w >> 1, wn = w & 1;
    const int g = lane >> 2, t4 = lane & 3, mi = lane >> 3, r8 = lane & 7;
    const int la = lane & 15, ha = lane >> 4;
    const __half* Bsrc = g_ao16 + (size_t)n * CC * HWD;

    auto prefetch = [&](int buf, int k0) {
        __half* Ab = GS + buf * GA_ST;
        __half* Bb = GS + GB_OFF + buf * GB_ST;
        #pragma unroll
        for (int i = 0; i < 2; i++) {
            int s = tid + 256 * i;
            int row = s >> 2, c8 = (s & 3) * 8;
            cp16(&Ab[row * 40 + c8], &g_pw16[(size_t)(o0 + row) * CC + k0 + c8]);
        }
        #pragma unroll
        for (int i = 0; i < 2; i++) {
            int s = tid + 256 * i;
            int row = s >> 4, c8 = (s & 15) * 8;
            cp16(&Bb[row * 136 + c8], &Bsrc[(size_t)(k0 + row) * HWD + j0 + c8]);
        }
        asm volatile("cp.async.commit_group;\n");
    };

    float acc[2][8][4] = {};
    prefetch(0, 0);
    prefetch(1, 32);
    for (int c = 0; c < 8; c++) {
        if (c < 7) asm volatile("cp.async.wait_group 1;\n");
        else       asm volatile("cp.async.wait_group 0;\n");
        __syncthreads();
        if (c + 2 < 8) prefetch((c + 2) % 3, (c + 2) * 32);
        int buf = c % 3;
        __half* Ab = GS + buf * GA_ST;
        __half* Bb = GS + GB_OFF + buf * GB_ST;
        #pragma unroll
        for (int ks = 0; ks < 2; ks++) {
            uint32_t a[2][4];
            #pragma unroll
            for (int mt = 0; mt < 2; mt++)
                ldsm4(a[mt], &Ab[(wm * 32 + mt * 16 + la) * 40 + ks * 16 + ha * 8]);
            #pragma unroll
            for (int nb = 0; nb < 4; nb++) {
                uint32_t b[4];
                ldsm4t(b, &Bb[(ks * 16 + (mi & 1) * 8 + r8) * 136 + wn * 64 + nb * 16 + (mi >> 1) * 8]);
                #pragma unroll
                for (int mt = 0; mt < 2; mt++) {
                    mma16816(acc[mt][2 * nb],     a[mt], b[0], b[1]);
                    mma16816(acc[mt][2 * nb + 1], a[mt], b[2], b[3]);
                }
            }
        }
    }

    #pragma unroll
    for (int mt = 0; mt < 2; mt++) {
        int o_lo = o0 + wm * 32 + mt * 16 + g;
        float b_lo = pb[o_lo], b_hi = pb[o_lo + 8];
        #pragma unroll
        for (int nt = 0; nt < 8; nt++) {
            int j = j0 + wn * 64 + nt * 8 + 2 * t4;
            float2 mv = *(const float2*)&mask[(size_t)n * HWD + j];
            size_t off = ((size_t)n * CC + o_lo) * HWD + j;
            float2 xv = *(const float2*)&x[off];
            float2 r;
            r.x = (xv.x + acc[mt][nt][0] + b_lo) * mv.x;
            r.y = (xv.y + acc[mt][nt][1] + b_lo) * mv.y;
            *(float2*)&out[off] = r;
            size_t off2 = off + 8 * HWD;
            float2 xv2 = *(const float2*)&x[off2];
            float2 r2;
            r2.x = (xv2.x + acc[mt][nt][2] + b_hi) * mv.x;
            r2.y = (xv2.y + acc[mt][nt][3] + b_hi) * mv.y;
            *(float2*)&out[off2] = r2;
        }
    }
}

// ---------------- Flash attention: split-K x2, fixed-bias softmax, f16 partials ----------------
#define KP 72
#define QP 136
#define BIAS_H2 0xC800C800u   // f16x2 {-8, -8}
__global__ __launch_bounds__(128, 3) void attn_kernel() {
    __shared__ __align__(16) __half SMh[18432];   // 36864 B
    const int n = blockIdx.y >> 2, h = blockIdx.y & 3;
    const int q0 = blockIdx.x * 128;
    const int split = blockIdx.z;
    const int c0 = split * CHUNKS_PER_SPLIT;
    const size_t base = (size_t)(n * CC + h * HD) * HWD;
    const __half* qg = g_q16 + base;
    const __half* kg = g_k16 + base;
    const __half* vg = g_v16 + base;

    const int tid = threadIdx.x, w = tid >> 5, lane = tid & 31;
    const int g = lane >> 2, t4 = lane & 3, mi = lane >> 3, r8 = lane & 7;

    #pragma unroll
    for (int i = 0; i < 8; i++) {
        int s = tid + 128 * i;
        int row = s >> 4, c8 = (s & 15) * 8;
        *(uint4*)&SMh[row * QP + c8] = *(const uint4*)&qg[(size_t)row * HWD + q0 + c8];
    }
    __syncthreads();
    uint32_t aq[2][4][4];
    #pragma unroll
    for (int mt = 0; mt < 2; mt++)
        #pragma unroll
        for (int kt = 0; kt < 4; kt++)
            ldsm4t(aq[mt][kt],
                   &SMh[(kt * 16 + (mi >> 1) * 8 + r8) * QP + w * 32 + mt * 16 + (mi & 1) * 8]);
    __syncthreads();

    auto prefetch = [&](int buf, int c) {
        int jc = c * 64;
        __half* Kb = &SMh[buf * 4608];
        __half* Vb = &SMh[9216 + buf * 4608];
        #pragma unroll
        for (int i = 0; i < 4; i++) {
            int s = tid + 128 * i;
            int row = s >> 3, c8 = (s & 7) * 8;
            cp16(&Kb[row * KP + c8], &kg[(size_t)row * HWD + jc + c8]);
            cp16(&Vb[row * KP + c8], &vg[(size_t)row * HWD + jc + c8]);
        }
        asm volatile("cp.async.commit_group;\n");
    };

    float o_[2][8][4] = {};
    float l[2][2] = {};

    prefetch(0, c0);
    for (int c = c0; c < c0 + CHUNKS_PER_SPLIT; c++) {
        int buf = c & 1;
        if (c + 1 < c0 + CHUNKS_PER_SPLIT) { prefetch(buf ^ 1, c + 1); asm volatile("cp.async.wait_group 1;\n"); }
        else                               { asm volatile("cp.async.wait_group 0;\n"); }
        __syncthreads();
        const __half* Kb = &SMh[buf * 4608];
        const __half* Vb = &SMh[9216 + buf * 4608];

        // S = Q K^T + (-8), f16 accumulators
        uint32_t s[2][8][2];
        #pragma unroll
        for (int mt = 0; mt < 2; mt++)
            #pragma unroll
            for (int nt = 0; nt < 8; nt++) { s[mt][nt][0] = BIAS_H2; s[mt][nt][1] = BIAS_H2; }
        #pragma unroll
        for (int kt = 0; kt < 4; kt++) {
            #pragma unroll
            for (int ntp = 0; ntp < 4; ntp++) {
                uint32_t b[4];
                ldsm4t(b, &Kb[(kt * 16 + (mi & 1) * 8 + r8) * KP + ntp * 16 + (mi >> 1) * 8]);
                #pragma unroll
                for (int mt = 0; mt < 2; mt++) {
                    mma16816h(s[mt][2 * ntp],     aq[mt][kt], b[0], b[1]);
                    mma16816h(s[mt][2 * ntp + 1], aq[mt][kt], b[2], b[3]);
                }
            }
        }

        // p = exp2(s - 8) in place; accumulate row sums
        #pragma unroll
        for (int mt = 0; mt < 2; mt++) {
            __half2 hs0 = __floats2half2_rn(0.f, 0.f), hs1 = hs0;
            #pragma unroll
            for (int nt = 0; nt < 8; nt++) {
                uint32_t p0 = h2ex2(s[mt][nt][0]);
                uint32_t p1 = h2ex2(s[mt][nt][1]);
                s[mt][nt][0] = p0; s[mt][nt][1] = p1;
                hs0 = __hadd2(hs0, u2h(p0));
                hs1 = __hadd2(hs1, u2h(p1));
            }
            l[mt][0] += __low2float(hs0) + __high2float(hs0);
            l[mt][1] += __low2float(hs1) + __high2float(hs1);
        }

        // O += P V   (P aliases S)
        #pragma unroll
        for (int kt = 0; kt < 4; kt++) {
            #pragma unroll
            for (int ntp = 0; ntp < 4; ntp++) {
                uint32_t b[4];
                ldsm4(b, &Vb[(ntp * 16 + (mi >> 1) * 8 + r8) * KP + kt * 16 + (mi & 1) * 8]);
                #pragma unroll
                for (int mt = 0; mt < 2; mt++) {
                    uint32_t ap[4] = { s[mt][2 * kt][0], s[mt][2 * kt][1],
                                       s[mt][2 * kt + 1][0], s[mt][2 * kt + 1][1] };
                    mma16816(o_[mt][2 * ntp],     ap, b[0], b[1]);
                    mma16816(o_[mt][2 * ntp + 1], ap, b[2], b[3]);
                }
            }
        }
        __syncthreads();
    }

    // partial epilogue: quad row sums for l, write l (f32) + un-normalized O (f16)
    #pragma unroll
    for (int mt = 0; mt < 2; mt++)
        #pragma unroll
        for (int hh = 0; hh < 2; hh++) {
            l[mt][hh] += __shfl_xor_sync(0xffffffffu, l[mt][hh], 1);
            l[mt][hh] += __shfl_xor_sync(0xffffffffu, l[mt][hh], 2);
        }
    float* pl = g_pl + (size_t)split * NB * NH * HWD + (size_t)(n * NH + h) * HWD + q0;
    if (t4 == 0) {
        #pragma unroll
        for (int mt = 0; mt < 2; mt++) {
            int qr = w * 32 + mt * 16 + g;
            pl[qr]     = l[mt][0];
            pl[qr + 8] = l[mt][1];
        }
    }

    __syncthreads();
    #pragma unroll
    for (int mt = 0; mt < 2; mt++) {
        int qr = w * 32 + mt * 16 + g;
        #pragma unroll
        for (int nt = 0; nt < 8; nt++) {
            int d0 = nt * 8 + 2 * t4;
            *(uint32_t*)&SMh[qr * KP + d0]       = pack2(o_[mt][nt][0], o_[mt][nt][1]);
            *(uint32_t*)&SMh[(qr + 8) * KP + d0] = pack2(o_[mt][nt][2], o_[mt][nt][3]);
        }
    }
    __syncthreads();
    __half* po = g_po16 + (size_t)split * SPLIT_OFF + base;
    #pragma unroll
    for (int i = 0; i < 32; i++) {
        int f = tid + 128 * i;
        int qp = f & 63, d = f >> 6;
        __half2 hv = __halves2half2(SMh[(2 * qp) * KP + d], SMh[(2 * qp + 1) * KP + d]);
        *(uint32_t*)&po[(size_t)d * HWD + q0 + 2 * qp] = *(uint32_t*)&hv;
    }
}

// ---------------- split-K reduce: high-parallelism streaming combine ----------------
__global__ __launch_bounds__(256) void attn_reduce_kernel() {
    const int jt = blockIdx.x, nh = blockIdx.y, ds = blockIdx.z;
    const int n = nh >> 2, h = nh & 3;
    const int j0 = jt * 128;
    const int d0 = ds * 16;
    __shared__ float linv[128];
    const int tid = threadIdx.x;
    if (tid < 128) {
        size_t off = (size_t)nh * HWD + j0 + tid;
        linv[tid] = 1.0f / (g_pl[off] + g_pl[(size_t)NB * NH * HWD + off]);
    }
    __syncthreads();
    const size_t base = ((size_t)n * CC + h * HD + d0) * HWD;
    #pragma unroll
    for (int i = 0; i < 2; i++) {
        int f = tid + 256 * i;
        int d = f >> 5, qq = (f & 31) * 4;
        size_t off = base + (size_t)d * HWD + j0 + qq;
        uint2 a = *(const uint2*)&g_po16[off];
        uint2 b = *(const uint2*)&g_po16[SPLIT_OFF + off];
        __half2 a0 = u2h(a.x), a1 = u2h(a.y), b0 = u2h(b.x), b1 = u2h(b.y);
        float r0 = (__low2float(a0)  + __low2float(b0))  * linv[qq];
        float r1 = (__high2float(a0) + __high2float(b0)) * linv[qq + 1];
        float r2 = (__low2float(a1)  + __low2float(b1))  * linv[qq + 2];
        float r3 = (__high2float(a1) + __high2float(b1)) * linv[qq + 3];
        uint2 o;
        o.x = pack2(r0, r1);
        o.y = pack2(r2, r3);
        *(uint2*)&g_ao16[off] = o;
    }
}

// ---------------------------------------------------------------------------
extern "C" void kernel_launch(void* const* d_in, const int* in_sizes, int n_in,
                              void* d_out, int out_size) {
    const float* x      = (const float*)d_in[0];
    const float* mask   = (const float*)d_in[1];
    const float* norm_w = (const float*)d_in[2];
    const float* norm_b = (const float*)d_in[3];
    const float* qkv_w  = (const float*)d_in[4];
    const float* qkv_b  = (const float*)d_in[5];
    const float* proj_w = (const float*)d_in[6];
    const float* proj_b = (const float*)d_in[7];
    float* out = (float*)d_out;

    cudaFuncSetAttribute(gemm_qkv16_kernel,  cudaFuncAttributeMaxDynamicSharedMemorySize, QKV_SMEM);
    cudaFuncSetAttribute(gemm_proj16_kernel, cudaFuncAttributeMaxDynamicSharedMemorySize, PROJ_SMEM);

    gn_conv_kernel<<<NB * NGRP * GNP + 1024, 256>>>(x, qkv_w, proj_w);
    gemm_qkv16_kernel<<<dim3(HWD / 128, (3 * CC) / 128, NB), 256, QKV_SMEM>>>(x, norm_w, norm_b, qkv_b);
    attn_kernel<<<dim3(HWD / 128, NB * NH, NSPLIT), 128>>>();
    attn_reduce_kernel<<<dim3(HWD / 128, NB * NH, 4), 256>>>();
    int ny = (out_size >= NB * CC * HWD + NB * HWD) ? 3 : 2;
    gemm_proj16_kernel<<<dim3(HWD / 128, ny, NB), 256, PROJ_SMEM>>>(x, mask, proj_b, out);
}